// round 13
// baseline (speedup 1.0000x reference)
#include <cuda_runtime.h>
#include <cuda_bf16.h>
#include <math.h>
#include <stdint.h>

// Problem constants (fixed shapes)
#define T_TOK 4096
#define DIM   512
#define FDIM  1024
#define NE    8
#define TOPK  2
#define NPAIR (T_TOK*TOPK)

// ---------------- device scratch (static; no runtime allocation) ----------------
__device__ int   g_cnt[NE];
__device__ int   g_list[NE*T_TOK];   // packed (token<<1)|k
__device__ float g_wgt [NE*T_TOK];
__device__ float g_sumP[NE];
__device__ float g_zsum;

// bf16 hi/lo splits (NATURAL layouts — no transpose)
__device__ __nv_bfloat16 g_xh[(size_t)T_TOK*DIM];
__device__ __nv_bfloat16 g_xl[(size_t)T_TOK*DIM];
__device__ __nv_bfloat16 g_gh[(size_t)NE*DIM*FDIM];  // gate [E][D][F]
__device__ __nv_bfloat16 g_gl[(size_t)NE*DIM*FDIM];
__device__ __nv_bfloat16 g_uh[(size_t)NE*DIM*FDIM];  // up   [E][D][F]
__device__ __nv_bfloat16 g_ul[(size_t)NE*DIM*FDIM];
__device__ __nv_bfloat16 g_dh[(size_t)NE*FDIM*DIM];  // down [E][F][D]
__device__ __nv_bfloat16 g_dl[(size_t)NE*FDIM*DIM];
__device__ __nv_bfloat16 g_hh[(size_t)NPAIR*FDIM];   // hidden hi
__device__ __nv_bfloat16 g_hl[(size_t)NPAIR*FDIM];   // hidden lo
__device__ float g_pout[(size_t)NPAIR*DIM];

// ================= PTX helpers (family-portable: sm_80+) =================
__device__ __forceinline__ uint32_t smem_u32(const void* p) {
    uint32_t a;
    asm("{ .reg .u64 t; cvta.to.shared.u64 t, %1; cvt.u32.u64 %0, t; }" : "=r"(a) : "l"(p));
    return a;
}
__device__ __forceinline__ void cp16(uint32_t dst, const void* src, uint32_t bytes) {
    asm volatile("cp.async.cg.shared.global [%0], [%1], 16, %2;"
                 :: "r"(dst), "l"(src), "r"(bytes) : "memory");
}
#define CP_COMMIT() asm volatile("cp.async.commit_group;" ::: "memory")
#define CP_WAITG(n) asm volatile("cp.async.wait_group %0;" :: "n"(n) : "memory")

__device__ __forceinline__ void ldsm_x4(uint32_t* r, uint32_t addr) {
    asm volatile("ldmatrix.sync.aligned.m8n8.x4.shared.b16 {%0,%1,%2,%3}, [%4];"
        : "=r"(r[0]), "=r"(r[1]), "=r"(r[2]), "=r"(r[3]) : "r"(addr));
}
__device__ __forceinline__ void ldsm_x4_t(uint32_t* r, uint32_t addr) {
    asm volatile("ldmatrix.sync.aligned.m8n8.x4.trans.shared.b16 {%0,%1,%2,%3}, [%4];"
        : "=r"(r[0]), "=r"(r[1]), "=r"(r[2]), "=r"(r[3]) : "r"(addr));
}
__device__ __forceinline__ void mma_bf16(float* d, const uint32_t* a, const uint32_t* b) {
    asm volatile("mma.sync.aligned.m16n8k16.row.col.f32.bf16.bf16.f32 "
        "{%0,%1,%2,%3}, {%4,%5,%6,%7}, {%8,%9}, {%0,%1,%2,%3};"
        : "+f"(d[0]), "+f"(d[1]), "+f"(d[2]), "+f"(d[3])
        : "r"(a[0]), "r"(a[1]), "r"(a[2]), "r"(a[3]), "r"(b[0]), "r"(b[1]));
}

__device__ __forceinline__ void split_bf16(float v, __nv_bfloat16& h, __nv_bfloat16& l) {
    h = __float2bfloat16(v);
    l = __float2bfloat16(v - __bfloat162float(h));
}

// ---------------- prep: zero accumulators + split x + split weights (one launch) ----------------
#define XN4  (T_TOK*DIM/4)          // 524288
#define WPER (NE*DIM*FDIM/4)        // 1048576 float4s per weight tensor
#define PREP_TOT (XN4 + 3*WPER)

__global__ void prep_kernel(const float* __restrict__ x,
                            const float* __restrict__ gw,
                            const float* __restrict__ uw,
                            const float* __restrict__ dw) {
    int i = blockIdx.x * blockDim.x + threadIdx.x;
    if (i < NE + 1) {
        if (i < NE) { g_cnt[i] = 0; g_sumP[i] = 0.f; }
        else        g_zsum = 0.f;
    }
    if (i >= PREP_TOT) return;

    const float* src;
    __nv_bfloat16 *oh, *ol;
    size_t j;
    if (i < XN4) { src = x; oh = g_xh; ol = g_xl; j = i; }
    else {
        int k = i - XN4;
        int which = k / WPER;
        j = k - which * WPER;
        src = (which == 0) ? gw : (which == 1) ? uw : dw;
        oh  = (which == 0) ? g_gh : (which == 1) ? g_uh : g_dh;
        ol  = (which == 0) ? g_gl : (which == 1) ? g_ul : g_dl;
    }
    float4 v = ((const float4*)src)[j];
    __nv_bfloat16 h0,h1,h2,h3,l0,l1,l2,l3;
    split_bf16(v.x,h0,l0); split_bf16(v.y,h1,l1);
    split_bf16(v.z,h2,l2); split_bf16(v.w,h3,l3);
    ((__nv_bfloat162*)oh)[2*j]   = __nv_bfloat162(h0,h1);
    ((__nv_bfloat162*)oh)[2*j+1] = __nv_bfloat162(h2,h3);
    ((__nv_bfloat162*)ol)[2*j]   = __nv_bfloat162(l0,l1);
    ((__nv_bfloat162*)ol)[2*j+1] = __nv_bfloat162(l2,l3);
}

// ---------------- router: warp-per-token (coalesced), block-aggregated atomics ----------------
#define RT_TOK 32
__global__ void __launch_bounds__(1024) router_kernel(const float* __restrict__ x,
                                                      const float* __restrict__ rw) {
    __shared__ float s_sumP[NE];
    __shared__ float s_zsum;
    __shared__ int   s_cnt[NE];
    __shared__ int   s_base[NE];
    __shared__ int   s_ebuf[NE][2*RT_TOK];
    __shared__ float s_wbuf[NE][2*RT_TOK];

    int tid  = threadIdx.x;
    int wrp  = tid >> 5;
    int lane = tid & 31;
    int tok  = blockIdx.x * RT_TOK + wrp;

    if (tid < NE) { s_sumP[tid] = 0.f; s_cnt[tid] = 0; }
    if (tid == NE) s_zsum = 0.f;
    __syncthreads();

    const float4* xp = (const float4*)(x + (size_t)tok * DIM);
    float4 xv[4];
#pragma unroll
    for (int i = 0; i < 4; i++) xv[i] = xp[lane * 4 + i];

    float logit[NE];
#pragma unroll
    for (int e = 0; e < NE; e++) {
        const float4* wp = (const float4*)(rw + (size_t)e * DIM);
        float acc = 0.f;
#pragma unroll
        for (int i = 0; i < 4; i++) {
            float4 w4 = wp[lane * 4 + i];
            acc += xv[i].x * w4.x + xv[i].y * w4.y + xv[i].z * w4.z + xv[i].w * w4.w;
        }
#pragma unroll
        for (int o = 16; o > 0; o >>= 1) acc += __shfl_xor_sync(0xffffffffu, acc, o);
        logit[e] = acc;
    }

    if (lane == 0) {
        float m = logit[0];
#pragma unroll
        for (int e = 1; e < NE; e++) m = fmaxf(m, logit[e]);
        float p[NE]; float se = 0.f;
#pragma unroll
        for (int e = 0; e < NE; e++) { p[e] = expf(logit[e] - m); se += p[e]; }
        float inv = 1.f / se;

        int i0 = 0; float v0 = -1.f;
#pragma unroll
        for (int e = 0; e < NE; e++) if (p[e] > v0) { v0 = p[e]; i0 = e; }
        int i1 = -1; float v1 = -1.f;
#pragma unroll
        for (int e = 0; e < NE; e++) if (e != i0 && p[e] > v1) { v1 = p[e]; i1 = e; }

        float s2 = v0 + v1;
        float w0 = v0 / s2, w1 = v1 / s2;

        int p0 = atomicAdd(&s_cnt[i0], 1);
        s_ebuf[i0][p0] = (tok << 1);
        s_wbuf[i0][p0] = w0;
        int p1 = atomicAdd(&s_cnt[i1], 1);
        s_ebuf[i1][p1] = (tok << 1) | 1;
        s_wbuf[i1][p1] = w1;

#pragma unroll
        for (int e = 0; e < NE; e++) atomicAdd(&s_sumP[e], p[e] * inv);
        float lse = m + logf(se);
        atomicAdd(&s_zsum, lse * lse);
    }
    __syncthreads();

    if (tid < NE) {
        s_base[tid] = atomicAdd(&g_cnt[tid], s_cnt[tid]);
        atomicAdd(&g_sumP[tid], s_sumP[tid]);
    }
    if (tid == NE) atomicAdd(&g_zsum, s_zsum);
    __syncthreads();

    if (wrp < NE * 4) {
        int e = wrp >> 2, q = wrp & 3;
        int c = s_cnt[e], b = s_base[e];
        for (int i = q * 32 + lane; i < c; i += 128) {
            g_list[e * T_TOK + b + i] = s_ebuf[e][i];
            g_wgt [e * T_TOK + b + i] = s_wbuf[e][i];
        }
    }
}

// ================= Phase A: gate/up persistent warp-MMA GEMM =================
// Tile M=64 x N=64 (R11 shape), K chunks of 64, 2-stage pipeline, 2 blocks/SM.
// Persistent: grid = 304 blocks stride over active (e, rowblk, colblk) tiles.
#define GU_STG  55296
#define GU_SMEM (1024 + 2*GU_STG)
#define GU_NCOL 16
#define GU_GRID 304

__global__ void __launch_bounds__(256, 2) gateup_mma_kernel() {
    extern __shared__ char smem[];
    uint32_t sb = smem_u32(smem);
    int tid = threadIdx.x, wid = tid >> 5, lid = tid & 31;
    int wm = wid >> 2, wn = wid & 3;
    int g = lid >> 2, t2 = (lid & 3) * 2;
    int* sTok = (int*)smem;

    int cnts[NE];
    int tOff[NE + 1];
    tOff[0] = 0;
#pragma unroll
    for (int e = 0; e < NE; e++) {
        cnts[e] = g_cnt[e];
        tOff[e + 1] = tOff[e] + ((cnts[e] + 63) >> 6) * GU_NCOL;
    }
    int total = tOff[NE];

    uint32_t laneO = (uint32_t)(((lid & 7) + ((lid >> 3) & 1) * 8) * 144 + ((lid >> 4) & 1) * 16);

    for (int idx = blockIdx.x; idx < total; idx += GU_GRID) {
        int e = 0;
#pragma unroll
        for (int k = 0; k < NE - 1; k++) if (idx >= tOff[k + 1]) e = k + 1;
        int local = idx - tOff[e];
        int row0 = (local >> 4) * 64;
        int col0 = (local & (GU_NCOL - 1)) * 64;
        int cnt  = cnts[e];

        for (int i = tid; i < 64; i += 256) {
            int r = row0 + i;
            sTok[i] = (r < cnt) ? g_list[e * T_TOK + r] : -1;
        }
        __syncthreads();

        const __nv_bfloat16* b0 = g_gh + (size_t)e * DIM * FDIM;
        const __nv_bfloat16* b1 = g_gl + (size_t)e * DIM * FDIM;
        const __nv_bfloat16* b2 = g_uh + (size_t)e * DIM * FDIM;
        const __nv_bfloat16* b3 = g_ul + (size_t)e * DIM * FDIM;

        float accg[2][2][4] = {}, accu[2][2][4] = {};

        auto stage = [&](int chunk) {
            int kt = chunk * 64;
            uint32_t bb = sb + 1024 + (uint32_t)(chunk & 1) * GU_STG;
#pragma unroll
            for (int it = 0; it < 4; it++) {
                int t = tid + it * 256;
                int arr = t >> 9, u = t & 511, row = u >> 3, seg = u & 7;
                int entry = sTok[row];
                uint32_t bytes = (entry >= 0) ? 16u : 0u;
                const __nv_bfloat16* src = (arr ? g_xl : g_xh)
                    + (size_t)((entry >= 0) ? (entry >> 1) : 0) * DIM + kt + seg * 8;
                cp16(bb + arr * 9216 + row * 144 + seg * 16, src, bytes);
            }
#pragma unroll
            for (int it = 0; it < 8; it++) {
                int t = tid + it * 256;
                int arr = t >> 9, u = t & 511, row = u >> 3, seg = u & 7;
                const __nv_bfloat16* src = (arr == 0) ? b0 : (arr == 1) ? b1 : (arr == 2) ? b2 : b3;
                cp16(bb + 18432 + arr * 9216 + row * 144 + seg * 16,
                     src + (size_t)(kt + row) * FDIM + col0 + seg * 8, 16u);
            }
        };

        stage(0); CP_COMMIT();
        for (int c = 0; c < 8; c++) {
            if (c + 1 < 8) { stage(c + 1); CP_COMMIT(); CP_WAITG(1); }
            else           { CP_WAITG(0); }
            __syncthreads();
            uint32_t bb = sb + 1024 + (uint32_t)(c & 1) * GU_STG;
            uint32_t aBase = bb + (uint32_t)(wm * 32) * 144 + laneO;
            uint32_t bBase = bb + 18432 + laneO + (uint32_t)(wn * 16) * 2;
#pragma unroll
            for (int kk = 0; kk < 4; kk++) {
                uint32_t ah[2][4], al[2][4];
#pragma unroll
                for (int mt = 0; mt < 2; mt++) {
                    uint32_t aa = aBase + mt * (16 * 144) + kk * 32;
                    ldsm_x4(ah[mt], aa);
                    ldsm_x4(al[mt], aa + 9216);
                }
                uint32_t ba = bBase + kk * (16 * 144);
                uint32_t bgh[4], bgl[4], buh[4], bul[4];
                ldsm_x4_t(bgh, ba);
                ldsm_x4_t(bgl, ba + 9216);
                ldsm_x4_t(buh, ba + 18432);
                ldsm_x4_t(bul, ba + 27648);
#pragma unroll
                for (int h = 0; h < 2; h++) {
#pragma unroll
                    for (int mt = 0; mt < 2; mt++) {
                        mma_bf16(accg[mt][h], ah[mt], bgh + h * 2);
                        mma_bf16(accg[mt][h], ah[mt], bgl + h * 2);
                        mma_bf16(accg[mt][h], al[mt], bgh + h * 2);
                        mma_bf16(accu[mt][h], ah[mt], buh + h * 2);
                        mma_bf16(accu[mt][h], ah[mt], bul + h * 2);
                        mma_bf16(accu[mt][h], al[mt], buh + h * 2);
                    }
                }
            }
            __syncthreads();
        }

#pragma unroll
        for (int mt = 0; mt < 2; mt++) {
            int r0 = wm * 32 + mt * 16 + g;
            int e0 = sTok[r0], e1 = sTok[r0 + 8];
#pragma unroll
            for (int h = 0; h < 2; h++) {
                int colg = col0 + wn * 16 + h * 8 + t2;
                const float* dg = accg[mt][h];
                const float* du = accu[mt][h];
                if (e0 >= 0) {
                    float h0 = du[0] * (dg[0] / (1.f + expf(-dg[0])));
                    float h1 = du[1] * (dg[1] / (1.f + expf(-dg[1])));
                    __nv_bfloat16 h0h, h0l, h1h, h1l;
                    split_bf16(h0, h0h, h0l); split_bf16(h1, h1h, h1l);
                    *(__nv_bfloat162*)(g_hh + (size_t)e0 * FDIM + colg) = __nv_bfloat162(h0h, h1h);
                    *(__nv_bfloat162*)(g_hl + (size_t)e0 * FDIM + colg) = __nv_bfloat162(h0l, h1l);
                }
                if (e1 >= 0) {
                    float h0 = du[2] * (dg[2] / (1.f + expf(-dg[2])));
                    float h1 = du[3] * (dg[3] / (1.f + expf(-dg[3])));
                    __nv_bfloat16 h0h, h0l, h1h, h1l;
                    split_bf16(h0, h0h, h0l); split_bf16(h1, h1h, h1l);
                    *(__nv_bfloat162*)(g_hh + (size_t)e1 * FDIM + colg) = __nv_bfloat162(h0h, h1h);
                    *(__nv_bfloat162*)(g_hl + (size_t)e1 * FDIM + colg) = __nv_bfloat162(h0l, h1l);
                }
            }
        }
        __syncthreads();   // protect sTok before next tile
    }
}

// ================= Phase B: down persistent warp-MMA GEMM =================
// Tile M=64 x N=64 (R11 shape), K=1024 in 16 chunks, 2-stage pipeline, 3 blocks/SM.
#define DN_STG  36864
#define DN_SMEM (1024 + 2*DN_STG)
#define DN_NCOL 8
#define DN_GRID 456

__global__ void __launch_bounds__(256, 3) down_mma_kernel() {
    extern __shared__ char smem[];
    uint32_t sb = smem_u32(smem);
    int tid = threadIdx.x, wid = tid >> 5, lid = tid & 31;
    int wm = wid >> 2, wn = wid & 3;
    int g = lid >> 2, t2 = (lid & 3) * 2;
    int*   sTok = (int*)smem;
    float* sW   = (float*)(smem + 256);

    int cnts[NE];
    int tOff[NE + 1];
    tOff[0] = 0;
#pragma unroll
    for (int e = 0; e < NE; e++) {
        cnts[e] = g_cnt[e];
        tOff[e + 1] = tOff[e] + ((cnts[e] + 63) >> 6) * DN_NCOL;
    }
    int total = tOff[NE];

    uint32_t laneO = (uint32_t)(((lid & 7) + ((lid >> 3) & 1) * 8) * 144 + ((lid >> 4) & 1) * 16);

    for (int idx = blockIdx.x; idx < total; idx += DN_GRID) {
        int e = 0;
#pragma unroll
        for (int k = 0; k < NE - 1; k++) if (idx >= tOff[k + 1]) e = k + 1;
        int local = idx - tOff[e];
        int row0 = (local >> 3) * 64;
        int col0 = (local & (DN_NCOL - 1)) * 64;
        int cnt  = cnts[e];

        for (int i = tid; i < 64; i += 256) {
            int r = row0 + i;
            sTok[i] = (r < cnt) ? g_list[e * T_TOK + r] : -1;
            sW[i]   = (r < cnt) ? g_wgt [e * T_TOK + r] : 0.f;
        }
        __syncthreads();

        const __nv_bfloat16* dh = g_dh + (size_t)e * FDIM * DIM;
        const __nv_bfloat16* dl = g_dl + (size_t)e * FDIM * DIM;

        float acc[2][2][4] = {};

        auto stage = [&](int chunk) {
            int kt = chunk * 64;
            uint32_t bb = sb + 1024 + (uint32_t)(chunk & 1) * DN_STG;
#pragma unroll
            for (int it = 0; it < 4; it++) {
                int t = tid + it * 256;
                int arr = t >> 9, u = t & 511, row = u >> 3, seg = u & 7;
                int entry = sTok[row];
                uint32_t bytes = (entry >= 0) ? 16u : 0u;
                const __nv_bfloat16* src = (arr ? g_hl : g_hh)
                    + (size_t)((entry >= 0) ? entry : 0) * FDIM + kt + seg * 8;
                cp16(bb + arr * 9216 + row * 144 + seg * 16, src, bytes);
            }
#pragma unroll
            for (int it = 0; it < 4; it++) {
                int t = tid + it * 256;
                int arr = t >> 9, u = t & 511, row = u >> 3, seg = u & 7;
                const __nv_bfloat16* src = (arr ? dl : dh)
                    + (size_t)(kt + row) * DIM + col0 + seg * 8;
                cp16(bb + 18432 + arr * 9216 + row * 144 + seg * 16, src, 16u);
            }
        };

        stage(0); CP_COMMIT();
        for (int c = 0; c < 16; c++) {
            if (c + 1 < 16) { stage(c + 1); CP_COMMIT(); CP_WAITG(1); }
            else            { CP_WAITG(0); }
            __syncthreads();
            uint32_t bb = sb + 1024 + (uint32_t)(c & 1) * DN_STG;
            uint32_t aBase = bb + (uint32_t)(wm * 32) * 144 + laneO;
            uint32_t bBase = bb + 18432 + laneO + (uint32_t)(wn * 16) * 2;
#pragma unroll
            for (int kk = 0; kk < 4; kk++) {
                uint32_t ah[2][4], al[2][4];
#pragma unroll
                for (int mt = 0; mt < 2; mt++) {
                    uint32_t aa = aBase + mt * (16 * 144) + kk * 32;
                    ldsm_x4(ah[mt], aa);
                    ldsm_x4(al[mt], aa + 9216);
                }
                uint32_t ba = bBase + kk * (16 * 144);
                uint32_t bh[4], bl[4];
                ldsm_x4_t(bh, ba);
                ldsm_x4_t(bl, ba + 9216);
#pragma unroll
                for (int h = 0; h < 2; h++) {
#pragma unroll
                    for (int mt = 0; mt < 2; mt++) {
                        mma_bf16(acc[mt][h], ah[mt], bh + h * 2);
                        mma_bf16(acc[mt][h], ah[mt], bl + h * 2);
                        mma_bf16(acc[mt][h], al[mt], bh + h * 2);
                    }
                }
            }
            __syncthreads();
        }

#pragma unroll
        for (int mt = 0; mt < 2; mt++) {
            int r0 = wm * 32 + mt * 16 + g;
            int e0 = sTok[r0], e1 = sTok[r0 + 8];
            float w0 = sW[r0], w1 = sW[r0 + 8];
#pragma unroll
            for (int h = 0; h < 2; h++) {
                int cg = col0 + wn * 16 + h * 8 + t2;
                const float* d = acc[mt][h];
                if (e0 >= 0) {
                    float2 o = make_float2(w0 * d[0], w0 * d[1]);
                    *(float2*)(g_pout + (size_t)e0 * DIM + cg) = o;
                }
                if (e1 >= 0) {
                    float2 o = make_float2(w1 * d[2], w1 * d[3]);
                    *(float2*)(g_pout + (size_t)e1 * DIM + cg) = o;
                }
            }
        }
        __syncthreads();   // protect sTok/sW before next tile
    }
}

// ---------------- combine pair slots + aux loss (fused) ----------------
__global__ void combine_kernel(float* __restrict__ out, int out_size) {
    int i = blockIdx.x * blockDim.x + threadIdx.x;
    if (blockIdx.x == 0 && threadIdx.x == 0) {
        float lb = 0.f;
#pragma unroll
        for (int e = 0; e < NE; e++)
            lb += ((float)g_cnt[e] / (float)NPAIR) * (g_sumP[e] / (float)T_TOK);
        out[out_size - 1] = 0.01f * (float)NE * lb + 0.001f * (g_zsum / (float)T_TOK);
    }
    const int N4 = T_TOK * DIM / 4;
    const int D4 = DIM / 4;
    if (i >= N4) return;
    int t = i / D4, c = i % D4;
    const float4* p = (const float4*)g_pout;
    float4 a = p[(size_t)(2 * t) * D4 + c];
    float4 b = p[(size_t)(2 * t + 1) * D4 + c];
    ((float4*)out)[i] = make_float4(a.x + b.x, a.y + b.y, a.z + b.z, a.w + b.w);
}

// ---------------- launch ----------------
extern "C" void kernel_launch(void* const* d_in, const int* in_sizes, int n_in,
                              void* d_out, int out_size) {
    const float* x  = (const float*)d_in[0];
    const float* rw = (const float*)d_in[1];
    const float* gw = (const float*)d_in[2];
    const float* uw = (const float*)d_in[3];
    const float* dw = (const float*)d_in[4];
    float* out = (float*)d_out;

    cudaFuncSetAttribute(gateup_mma_kernel, cudaFuncAttributeMaxDynamicSharedMemorySize, GU_SMEM);
    cudaFuncSetAttribute(down_mma_kernel,   cudaFuncAttributeMaxDynamicSharedMemorySize, DN_SMEM);

    prep_kernel<<<(PREP_TOT + 255) / 256, 256>>>(x, gw, uw, dw);
    router_kernel<<<T_TOK / RT_TOK, 1024>>>(x, rw);
    gateup_mma_kernel<<<GU_GRID, 256, GU_SMEM>>>();
    down_mma_kernel<<<DN_GRID, 256, DN_SMEM>>>();
    combine_kernel<<<(T_TOK * DIM / 4 + 255) / 256, 256>>>(out, out_size);
}

// round 14
// speedup vs baseline: 1.0492x; 1.0492x over previous
#include <cuda_runtime.h>
#include <cuda_bf16.h>
#include <math.h>
#include <stdint.h>

// Problem constants (fixed shapes)
#define T_TOK 4096
#define DIM   512
#define FDIM  1024
#define NE    8
#define TOPK  2
#define NPAIR (T_TOK*TOPK)

// ---------------- device scratch (static; no runtime allocation) ----------------
// INVARIANT: g_cnt/g_sumP/g_zsum are zero at kernel_launch entry (zero-init at load,
// re-zeroed at the end of combine_kernel every launch).
__device__ int   g_cnt[NE];
__device__ int   g_list[NE*T_TOK];   // packed (token<<1)|k
__device__ float g_wgt [NE*T_TOK];
__device__ float g_sumP[NE];
__device__ float g_zsum;

// bf16 hi/lo splits (NATURAL layouts — no transpose)
__device__ __nv_bfloat16 g_xh[(size_t)T_TOK*DIM];
__device__ __nv_bfloat16 g_xl[(size_t)T_TOK*DIM];
__device__ __nv_bfloat16 g_gh[(size_t)NE*DIM*FDIM];  // gate [E][D][F]
__device__ __nv_bfloat16 g_gl[(size_t)NE*DIM*FDIM];
__device__ __nv_bfloat16 g_uh[(size_t)NE*DIM*FDIM];  // up   [E][D][F]
__device__ __nv_bfloat16 g_ul[(size_t)NE*DIM*FDIM];
__device__ __nv_bfloat16 g_dh[(size_t)NE*FDIM*DIM];  // down [E][F][D]
__device__ __nv_bfloat16 g_dl[(size_t)NE*FDIM*DIM];
__device__ __nv_bfloat16 g_hh[(size_t)NPAIR*FDIM];   // hidden hi
__device__ __nv_bfloat16 g_hl[(size_t)NPAIR*FDIM];   // hidden lo
__device__ float g_pout[(size_t)NPAIR*DIM];

// ================= PTX helpers (family-portable: sm_80+) =================
__device__ __forceinline__ uint32_t smem_u32(const void* p) {
    uint32_t a;
    asm("{ .reg .u64 t; cvta.to.shared.u64 t, %1; cvt.u32.u64 %0, t; }" : "=r"(a) : "l"(p));
    return a;
}
__device__ __forceinline__ void cp16(uint32_t dst, const void* src, uint32_t bytes) {
    asm volatile("cp.async.cg.shared.global [%0], [%1], 16, %2;"
                 :: "r"(dst), "l"(src), "r"(bytes) : "memory");
}
#define CP_COMMIT() asm volatile("cp.async.commit_group;" ::: "memory")
#define CP_WAITG(n) asm volatile("cp.async.wait_group %0;" :: "n"(n) : "memory")

__device__ __forceinline__ void ldsm_x4(uint32_t* r, uint32_t addr) {
    asm volatile("ldmatrix.sync.aligned.m8n8.x4.shared.b16 {%0,%1,%2,%3}, [%4];"
        : "=r"(r[0]), "=r"(r[1]), "=r"(r[2]), "=r"(r[3]) : "r"(addr));
}
__device__ __forceinline__ void ldsm_x4_t(uint32_t* r, uint32_t addr) {
    asm volatile("ldmatrix.sync.aligned.m8n8.x4.trans.shared.b16 {%0,%1,%2,%3}, [%4];"
        : "=r"(r[0]), "=r"(r[1]), "=r"(r[2]), "=r"(r[3]) : "r"(addr));
}
__device__ __forceinline__ void mma_bf16(float* d, const uint32_t* a, const uint32_t* b) {
    asm volatile("mma.sync.aligned.m16n8k16.row.col.f32.bf16.bf16.f32 "
        "{%0,%1,%2,%3}, {%4,%5,%6,%7}, {%8,%9}, {%0,%1,%2,%3};"
        : "+f"(d[0]), "+f"(d[1]), "+f"(d[2]), "+f"(d[3])
        : "r"(a[0]), "r"(a[1]), "r"(a[2]), "r"(a[3]), "r"(b[0]), "r"(b[1]));
}

__device__ __forceinline__ void split_bf16(float v, __nv_bfloat16& h, __nv_bfloat16& l) {
    h = __float2bfloat16(v);
    l = __float2bfloat16(v - __bfloat162float(h));
}

// ---------------- fused router + prep (one launch, disjoint block ranges) ----------------
// Blocks [0, RT_BLKS): router, 8 warps = 8 tokens each (needs g_cnt==0 at entry).
// Blocks [RT_BLKS, RT_BLKS+PREP_BLKS): hi/lo split of x and all weights.
#define RT_TOK    8
#define RT_BLKS   (T_TOK / RT_TOK)                 // 512
#define XN4       (T_TOK*DIM/4)                    // 524288
#define WPER      (NE*DIM*FDIM/4)                  // 1048576
#define PREP_TOT  (XN4 + 3*WPER)                   // 3670016
#define PREP_BLKS ((PREP_TOT + 255) / 256)         // 14336

__global__ void __launch_bounds__(256) prep_router_kernel(const float* __restrict__ x,
                                                          const float* __restrict__ rw,
                                                          const float* __restrict__ gw,
                                                          const float* __restrict__ uw,
                                                          const float* __restrict__ dw) {
    if (blockIdx.x < RT_BLKS) {
        // ---------------- router part ----------------
        __shared__ float s_sumP[NE];
        __shared__ float s_zsum;
        __shared__ int   s_cnt[NE];
        __shared__ int   s_base[NE];
        __shared__ int   s_ebuf[NE][2*RT_TOK];
        __shared__ float s_wbuf[NE][2*RT_TOK];

        int tid  = threadIdx.x;
        int wrp  = tid >> 5;
        int lane = tid & 31;
        int tok  = blockIdx.x * RT_TOK + wrp;

        if (tid < NE) { s_sumP[tid] = 0.f; s_cnt[tid] = 0; }
        if (tid == NE) s_zsum = 0.f;
        __syncthreads();

        const float4* xp = (const float4*)(x + (size_t)tok * DIM);
        float4 xv[4];
#pragma unroll
        for (int i = 0; i < 4; i++) xv[i] = xp[lane * 4 + i];

        float logit[NE];
#pragma unroll
        for (int e = 0; e < NE; e++) {
            const float4* wp = (const float4*)(rw + (size_t)e * DIM);
            float acc = 0.f;
#pragma unroll
            for (int i = 0; i < 4; i++) {
                float4 w4 = wp[lane * 4 + i];
                acc += xv[i].x * w4.x + xv[i].y * w4.y + xv[i].z * w4.z + xv[i].w * w4.w;
            }
#pragma unroll
            for (int o = 16; o > 0; o >>= 1) acc += __shfl_xor_sync(0xffffffffu, acc, o);
            logit[e] = acc;
        }

        if (lane == 0) {
            float m = logit[0];
#pragma unroll
            for (int e = 1; e < NE; e++) m = fmaxf(m, logit[e]);
            float p[NE]; float se = 0.f;
#pragma unroll
            for (int e = 0; e < NE; e++) { p[e] = expf(logit[e] - m); se += p[e]; }
            float inv = 1.f / se;

            int i0 = 0; float v0 = -1.f;
#pragma unroll
            for (int e = 0; e < NE; e++) if (p[e] > v0) { v0 = p[e]; i0 = e; }
            int i1 = -1; float v1 = -1.f;
#pragma unroll
            for (int e = 0; e < NE; e++) if (e != i0 && p[e] > v1) { v1 = p[e]; i1 = e; }

            float s2 = v0 + v1;
            float w0 = v0 / s2, w1 = v1 / s2;

            int p0 = atomicAdd(&s_cnt[i0], 1);
            s_ebuf[i0][p0] = (tok << 1);
            s_wbuf[i0][p0] = w0;
            int p1 = atomicAdd(&s_cnt[i1], 1);
            s_ebuf[i1][p1] = (tok << 1) | 1;
            s_wbuf[i1][p1] = w1;

#pragma unroll
            for (int e = 0; e < NE; e++) atomicAdd(&s_sumP[e], p[e] * inv);
            float lse = m + logf(se);
            atomicAdd(&s_zsum, lse * lse);
        }
        __syncthreads();

        if (tid < NE) {
            s_base[tid] = atomicAdd(&g_cnt[tid], s_cnt[tid]);
            atomicAdd(&g_sumP[tid], s_sumP[tid]);
        }
        if (tid == NE) atomicAdd(&g_zsum, s_zsum);
        __syncthreads();

        // copy-out: warp e handles expert e (8 warps, 8 experts)
        {
            int e = wrp;
            int c = s_cnt[e], b = s_base[e];
            if (lane < c) {
                g_list[e * T_TOK + b + lane] = s_ebuf[e][lane];
                g_wgt [e * T_TOK + b + lane] = s_wbuf[e][lane];
            }
        }
        return;
    }

    // ---------------- prep part ----------------
    int i = (blockIdx.x - RT_BLKS) * blockDim.x + threadIdx.x;
    if (i >= PREP_TOT) return;

    const float* src;
    __nv_bfloat16 *oh, *ol;
    size_t j;
    if (i < XN4) { src = x; oh = g_xh; ol = g_xl; j = i; }
    else {
        int k = i - XN4;
        int which = k / WPER;
        j = k - which * WPER;
        src = (which == 0) ? gw : (which == 1) ? uw : dw;
        oh  = (which == 0) ? g_gh : (which == 1) ? g_uh : g_dh;
        ol  = (which == 0) ? g_gl : (which == 1) ? g_ul : g_dl;
    }
    float4 v = ((const float4*)src)[j];
    __nv_bfloat16 h0,h1,h2,h3,l0,l1,l2,l3;
    split_bf16(v.x,h0,l0); split_bf16(v.y,h1,l1);
    split_bf16(v.z,h2,l2); split_bf16(v.w,h3,l3);
    ((__nv_bfloat162*)oh)[2*j]   = __nv_bfloat162(h0,h1);
    ((__nv_bfloat162*)oh)[2*j+1] = __nv_bfloat162(h2,h3);
    ((__nv_bfloat162*)ol)[2*j]   = __nv_bfloat162(l0,l1);
    ((__nv_bfloat162*)ol)[2*j+1] = __nv_bfloat162(l2,l3);
}

// ================= Phase A: gate/up warp-MMA GEMM (R11 exact) =================
#define GU_STG  55296
#define GU_SMEM (1024 + 2*GU_STG)

__global__ void __launch_bounds__(256, 2) gateup_mma_kernel() {
    extern __shared__ char smem[];
    uint32_t sb = smem_u32(smem);
    int e = blockIdx.z;
    int cnt = g_cnt[e];
    int row0 = blockIdx.y * 64;
    if (row0 >= cnt) return;
    int col0 = blockIdx.x * 64;
    int tid = threadIdx.x, wid = tid >> 5, lid = tid & 31;
    int wm = wid >> 2, wn = wid & 3;
    int g = lid >> 2, t2 = (lid & 3) * 2;
    int* sTok = (int*)smem;

    for (int i = tid; i < 64; i += 256) {
        int r = row0 + i;
        sTok[i] = (r < cnt) ? g_list[e * T_TOK + r] : -1;
    }
    __syncthreads();

    const __nv_bfloat16* b0 = g_gh + (size_t)e * DIM * FDIM;
    const __nv_bfloat16* b1 = g_gl + (size_t)e * DIM * FDIM;
    const __nv_bfloat16* b2 = g_uh + (size_t)e * DIM * FDIM;
    const __nv_bfloat16* b3 = g_ul + (size_t)e * DIM * FDIM;

    float accg[2][2][4] = {}, accu[2][2][4] = {};

    auto stage = [&](int chunk) {
        int kt = chunk * 64;
        uint32_t bb = sb + 1024 + (uint32_t)(chunk & 1) * GU_STG;
#pragma unroll
        for (int it = 0; it < 4; it++) {
            int t = tid + it * 256;
            int arr = t >> 9, u = t & 511, row = u >> 3, seg = u & 7;
            int entry = sTok[row];
            uint32_t bytes = (entry >= 0) ? 16u : 0u;
            const __nv_bfloat16* src = (arr ? g_xl : g_xh)
                + (size_t)((entry >= 0) ? (entry >> 1) : 0) * DIM + kt + seg * 8;
            cp16(bb + arr * 9216 + row * 144 + seg * 16, src, bytes);
        }
#pragma unroll
        for (int it = 0; it < 8; it++) {
            int t = tid + it * 256;
            int arr = t >> 9, u = t & 511, row = u >> 3, seg = u & 7;
            const __nv_bfloat16* src = (arr == 0) ? b0 : (arr == 1) ? b1 : (arr == 2) ? b2 : b3;
            cp16(bb + 18432 + arr * 9216 + row * 144 + seg * 16,
                 src + (size_t)(kt + row) * FDIM + col0 + seg * 8, 16u);
        }
    };

    uint32_t laneO = (uint32_t)(((lid & 7) + ((lid >> 3) & 1) * 8) * 144 + ((lid >> 4) & 1) * 16);

    stage(0); CP_COMMIT();
    for (int c = 0; c < 8; c++) {
        if (c + 1 < 8) { stage(c + 1); CP_COMMIT(); CP_WAITG(1); }
        else           { CP_WAITG(0); }
        __syncthreads();
        uint32_t bb = sb + 1024 + (uint32_t)(c & 1) * GU_STG;
        uint32_t aBase = bb + (uint32_t)(wm * 32) * 144 + laneO;
        uint32_t bBase = bb + 18432 + laneO + (uint32_t)(wn * 16) * 2;
#pragma unroll
        for (int kk = 0; kk < 4; kk++) {
            uint32_t ah[2][4], al[2][4];
#pragma unroll
            for (int mt = 0; mt < 2; mt++) {
                uint32_t aa = aBase + mt * (16 * 144) + kk * 32;
                ldsm_x4(ah[mt], aa);
                ldsm_x4(al[mt], aa + 9216);
            }
            uint32_t ba = bBase + kk * (16 * 144);
            uint32_t bgh[4], bgl[4], buh[4], bul[4];
            ldsm_x4_t(bgh, ba);
            ldsm_x4_t(bgl, ba + 9216);
            ldsm_x4_t(buh, ba + 18432);
            ldsm_x4_t(bul, ba + 27648);
#pragma unroll
            for (int h = 0; h < 2; h++) {
#pragma unroll
                for (int mt = 0; mt < 2; mt++) {
                    mma_bf16(accg[mt][h], ah[mt], bgh + h * 2);
                    mma_bf16(accg[mt][h], ah[mt], bgl + h * 2);
                    mma_bf16(accg[mt][h], al[mt], bgh + h * 2);
                    mma_bf16(accu[mt][h], ah[mt], buh + h * 2);
                    mma_bf16(accu[mt][h], ah[mt], bul + h * 2);
                    mma_bf16(accu[mt][h], al[mt], buh + h * 2);
                }
            }
        }
        __syncthreads();
    }

#pragma unroll
    for (int mt = 0; mt < 2; mt++) {
        int r0 = wm * 32 + mt * 16 + g;
        int e0 = sTok[r0], e1 = sTok[r0 + 8];
#pragma unroll
        for (int h = 0; h < 2; h++) {
            int colg = col0 + wn * 16 + h * 8 + t2;
            const float* dg = accg[mt][h];
            const float* du = accu[mt][h];
            if (e0 >= 0) {
                float h0 = du[0] * (dg[0] / (1.f + expf(-dg[0])));
                float h1 = du[1] * (dg[1] / (1.f + expf(-dg[1])));
                __nv_bfloat16 h0h, h0l, h1h, h1l;
                split_bf16(h0, h0h, h0l); split_bf16(h1, h1h, h1l);
                *(__nv_bfloat162*)(g_hh + (size_t)e0 * FDIM + colg) = __nv_bfloat162(h0h, h1h);
                *(__nv_bfloat162*)(g_hl + (size_t)e0 * FDIM + colg) = __nv_bfloat162(h0l, h1l);
            }
            if (e1 >= 0) {
                float h0 = du[2] * (dg[2] / (1.f + expf(-dg[2])));
                float h1 = du[3] * (dg[3] / (1.f + expf(-dg[3])));
                __nv_bfloat16 h0h, h0l, h1h, h1l;
                split_bf16(h0, h0h, h0l); split_bf16(h1, h1h, h1l);
                *(__nv_bfloat162*)(g_hh + (size_t)e1 * FDIM + colg) = __nv_bfloat162(h0h, h1h);
                *(__nv_bfloat162*)(g_hl + (size_t)e1 * FDIM + colg) = __nv_bfloat162(h0l, h1l);
            }
        }
    }
}

// ================= Phase B: down warp-MMA GEMM (R11 exact) =================
#define DN_STG  36864
#define DN_SMEM (1024 + 2*DN_STG)

__global__ void __launch_bounds__(256, 3) down_mma_kernel() {
    extern __shared__ char smem[];
    uint32_t sb = smem_u32(smem);
    int e = blockIdx.z;
    int cnt = g_cnt[e];
    int row0 = blockIdx.y * 64;
    if (row0 >= cnt) return;
    int col0 = blockIdx.x * 64;
    int tid = threadIdx.x, wid = tid >> 5, lid = tid & 31;
    int wm = wid >> 2, wn = wid & 3;
    int g = lid >> 2, t2 = (lid & 3) * 2;
    int*   sTok = (int*)smem;
    float* sW   = (float*)(smem + 256);

    for (int i = tid; i < 64; i += 256) {
        int r = row0 + i;
        sTok[i] = (r < cnt) ? g_list[e * T_TOK + r] : -1;
        sW[i]   = (r < cnt) ? g_wgt [e * T_TOK + r] : 0.f;
    }
    __syncthreads();

    const __nv_bfloat16* dh = g_dh + (size_t)e * FDIM * DIM;
    const __nv_bfloat16* dl = g_dl + (size_t)e * FDIM * DIM;

    float acc[2][2][4] = {};

    auto stage = [&](int chunk) {
        int kt = chunk * 64;
        uint32_t bb = sb + 1024 + (uint32_t)(chunk & 1) * DN_STG;
#pragma unroll
        for (int it = 0; it < 4; it++) {
            int t = tid + it * 256;
            int arr = t >> 9, u = t & 511, row = u >> 3, seg = u & 7;
            int entry = sTok[row];
            uint32_t bytes = (entry >= 0) ? 16u : 0u;
            const __nv_bfloat16* src = (arr ? g_hl : g_hh)
                + (size_t)((entry >= 0) ? entry : 0) * FDIM + kt + seg * 8;
            cp16(bb + arr * 9216 + row * 144 + seg * 16, src, bytes);
        }
#pragma unroll
        for (int it = 0; it < 4; it++) {
            int t = tid + it * 256;
            int arr = t >> 9, u = t & 511, row = u >> 3, seg = u & 7;
            const __nv_bfloat16* src = (arr ? dl : dh)
                + (size_t)(kt + row) * DIM + col0 + seg * 8;
            cp16(bb + 18432 + arr * 9216 + row * 144 + seg * 16, src, 16u);
        }
    };

    uint32_t laneO = (uint32_t)(((lid & 7) + ((lid >> 3) & 1) * 8) * 144 + ((lid >> 4) & 1) * 16);

    stage(0); CP_COMMIT();
    for (int c = 0; c < 16; c++) {
        if (c + 1 < 16) { stage(c + 1); CP_COMMIT(); CP_WAITG(1); }
        else            { CP_WAITG(0); }
        __syncthreads();
        uint32_t bb = sb + 1024 + (uint32_t)(c & 1) * DN_STG;
        uint32_t aBase = bb + (uint32_t)(wm * 32) * 144 + laneO;
        uint32_t bBase = bb + 18432 + laneO + (uint32_t)(wn * 16) * 2;
#pragma unroll
        for (int kk = 0; kk < 4; kk++) {
            uint32_t ah[2][4], al[2][4];
#pragma unroll
            for (int mt = 0; mt < 2; mt++) {
                uint32_t aa = aBase + mt * (16 * 144) + kk * 32;
                ldsm_x4(ah[mt], aa);
                ldsm_x4(al[mt], aa + 9216);
            }
            uint32_t ba = bBase + kk * (16 * 144);
            uint32_t bh[4], bl[4];
            ldsm_x4_t(bh, ba);
            ldsm_x4_t(bl, ba + 9216);
#pragma unroll
            for (int h = 0; h < 2; h++) {
#pragma unroll
                for (int mt = 0; mt < 2; mt++) {
                    mma_bf16(acc[mt][h], ah[mt], bh + h * 2);
                    mma_bf16(acc[mt][h], ah[mt], bl + h * 2);
                    mma_bf16(acc[mt][h], al[mt], bh + h * 2);
                }
            }
        }
        __syncthreads();
    }

#pragma unroll
    for (int mt = 0; mt < 2; mt++) {
        int r0 = wm * 32 + mt * 16 + g;
        int e0 = sTok[r0], e1 = sTok[r0 + 8];
        float w0 = sW[r0], w1 = sW[r0 + 8];
#pragma unroll
        for (int h = 0; h < 2; h++) {
            int cg = col0 + wn * 16 + h * 8 + t2;
            const float* d = acc[mt][h];
            if (e0 >= 0) {
                float2 o = make_float2(w0 * d[0], w0 * d[1]);
                *(float2*)(g_pout + (size_t)e0 * DIM + cg) = o;
            }
            if (e1 >= 0) {
                float2 o = make_float2(w1 * d[2], w1 * d[3]);
                *(float2*)(g_pout + (size_t)e1 * DIM + cg) = o;
            }
        }
    }
}

// ---------------- combine pair slots + aux loss + reset accumulators ----------------
__global__ void combine_kernel(float* __restrict__ out, int out_size) {
    int i = blockIdx.x * blockDim.x + threadIdx.x;
    if (blockIdx.x == 0 && threadIdx.x == 0) {
        float lb = 0.f;
#pragma unroll
        for (int e = 0; e < NE; e++)
            lb += ((float)g_cnt[e] / (float)NPAIR) * (g_sumP[e] / (float)T_TOK);
        out[out_size - 1] = 0.01f * (float)NE * lb + 0.001f * (g_zsum / (float)T_TOK);
        // restore the zero-invariant for the next launch (graph replay)
#pragma unroll
        for (int e = 0; e < NE; e++) { g_cnt[e] = 0; g_sumP[e] = 0.f; }
        g_zsum = 0.f;
    }
    const int N4 = T_TOK * DIM / 4;
    const int D4 = DIM / 4;
    if (i >= N4) return;
    int t = i / D4, c = i % D4;
    const float4* p = (const float4*)g_pout;
    float4 a = p[(size_t)(2 * t) * D4 + c];
    float4 b = p[(size_t)(2 * t + 1) * D4 + c];
    ((float4*)out)[i] = make_float4(a.x + b.x, a.y + b.y, a.z + b.z, a.w + b.w);
}

// ---------------- launch ----------------
extern "C" void kernel_launch(void* const* d_in, const int* in_sizes, int n_in,
                              void* d_out, int out_size) {
    const float* x  = (const float*)d_in[0];
    const float* rw = (const float*)d_in[1];
    const float* gw = (const float*)d_in[2];
    const float* uw = (const float*)d_in[3];
    const float* dw = (const float*)d_in[4];
    float* out = (float*)d_out;

    cudaFuncSetAttribute(gateup_mma_kernel, cudaFuncAttributeMaxDynamicSharedMemorySize, GU_SMEM);
    cudaFuncSetAttribute(down_mma_kernel,   cudaFuncAttributeMaxDynamicSharedMemorySize, DN_SMEM);

    prep_router_kernel<<<RT_BLKS + PREP_BLKS, 256>>>(x, rw, gw, uw, dw);
    gateup_mma_kernel<<<dim3(FDIM / 64, T_TOK / 64, NE), 256, GU_SMEM>>>();
    down_mma_kernel<<<dim3(DIM / 64, T_TOK / 64, NE), 256, DN_SMEM>>>();
    combine_kernel<<<(T_TOK * DIM / 4 + 255) / 256, 256>>>(out, out_size);
}

// round 15
// speedup vs baseline: 1.0718x; 1.0215x over previous
#include <cuda_runtime.h>
#include <cuda_bf16.h>
#include <math.h>
#include <stdint.h>

// Problem constants (fixed shapes)
#define T_TOK 4096
#define DIM   512
#define FDIM  1024
#define NE    8
#define TOPK  2
#define NPAIR (T_TOK*TOPK)

// ---------------- device scratch (static; no runtime allocation) ----------------
// INVARIANT: g_cnt/g_sumP/g_zsum are zero at kernel_launch entry (zero-init at load,
// re-zeroed by reset_kernel at the end of every launch).
__device__ int   g_cnt[NE];
__device__ int   g_list[NE*T_TOK];   // packed (token<<1)|k
__device__ float g_wgt [NE*T_TOK];
__device__ float g_sumP[NE];
__device__ float g_zsum;

// bf16 hi/lo splits (NATURAL layouts — no transpose)
__device__ __nv_bfloat16 g_xh[(size_t)T_TOK*DIM];
__device__ __nv_bfloat16 g_xl[(size_t)T_TOK*DIM];
__device__ __nv_bfloat16 g_gh[(size_t)NE*DIM*FDIM];  // gate [E][D][F]
__device__ __nv_bfloat16 g_gl[(size_t)NE*DIM*FDIM];
__device__ __nv_bfloat16 g_uh[(size_t)NE*DIM*FDIM];  // up   [E][D][F]
__device__ __nv_bfloat16 g_ul[(size_t)NE*DIM*FDIM];
__device__ __nv_bfloat16 g_dh[(size_t)NE*FDIM*DIM];  // down [E][F][D]
__device__ __nv_bfloat16 g_dl[(size_t)NE*FDIM*DIM];
__device__ __nv_bfloat16 g_hh[(size_t)NPAIR*FDIM];   // hidden hi
__device__ __nv_bfloat16 g_hl[(size_t)NPAIR*FDIM];   // hidden lo

// ================= PTX helpers (family-portable: sm_80+) =================
__device__ __forceinline__ uint32_t smem_u32(const void* p) {
    uint32_t a;
    asm("{ .reg .u64 t; cvta.to.shared.u64 t, %1; cvt.u32.u64 %0, t; }" : "=r"(a) : "l"(p));
    return a;
}
__device__ __forceinline__ void cp16(uint32_t dst, const void* src, uint32_t bytes) {
    asm volatile("cp.async.cg.shared.global [%0], [%1], 16, %2;"
                 :: "r"(dst), "l"(src), "r"(bytes) : "memory");
}
#define CP_COMMIT() asm volatile("cp.async.commit_group;" ::: "memory")
#define CP_WAITG(n) asm volatile("cp.async.wait_group %0;" :: "n"(n) : "memory")

__device__ __forceinline__ void ldsm_x4(uint32_t* r, uint32_t addr) {
    asm volatile("ldmatrix.sync.aligned.m8n8.x4.shared.b16 {%0,%1,%2,%3}, [%4];"
        : "=r"(r[0]), "=r"(r[1]), "=r"(r[2]), "=r"(r[3]) : "r"(addr));
}
__device__ __forceinline__ void ldsm_x4_t(uint32_t* r, uint32_t addr) {
    asm volatile("ldmatrix.sync.aligned.m8n8.x4.trans.shared.b16 {%0,%1,%2,%3}, [%4];"
        : "=r"(r[0]), "=r"(r[1]), "=r"(r[2]), "=r"(r[3]) : "r"(addr));
}
__device__ __forceinline__ void mma_bf16(float* d, const uint32_t* a, const uint32_t* b) {
    asm volatile("mma.sync.aligned.m16n8k16.row.col.f32.bf16.bf16.f32 "
        "{%0,%1,%2,%3}, {%4,%5,%6,%7}, {%8,%9}, {%0,%1,%2,%3};"
        : "+f"(d[0]), "+f"(d[1]), "+f"(d[2]), "+f"(d[3])
        : "r"(a[0]), "r"(a[1]), "r"(a[2]), "r"(a[3]), "r"(b[0]), "r"(b[1]));
}

__device__ __forceinline__ void split_bf16(float v, __nv_bfloat16& h, __nv_bfloat16& l) {
    h = __float2bfloat16(v);
    l = __float2bfloat16(v - __bfloat162float(h));
}

__device__ __forceinline__ void split4_store(const float4 v, __nv_bfloat16* oh,
                                             __nv_bfloat16* ol, size_t j) {
    __nv_bfloat16 h0,h1,h2,h3,l0,l1,l2,l3;
    split_bf16(v.x,h0,l0); split_bf16(v.y,h1,l1);
    split_bf16(v.z,h2,l2); split_bf16(v.w,h3,l3);
    ((__nv_bfloat162*)oh)[2*j]   = __nv_bfloat162(h0,h1);
    ((__nv_bfloat162*)oh)[2*j+1] = __nv_bfloat162(h2,h3);
    ((__nv_bfloat162*)ol)[2*j]   = __nv_bfloat162(l0,l1);
    ((__nv_bfloat162*)ol)[2*j+1] = __nv_bfloat162(l2,l3);
}

// ---------------- fused router + out-zero + x/gate/up split (one launch) ----------------
// Blocks [0, RT_BLKS): router (8 warps = 8 tokens each).
// Blocks [RT_BLKS, RT_BLKS+ZERO_BLKS): zero out[0, T_TOK*DIM).
// Blocks [.., +SPL_BLKS): hi/lo split of x, gate, up. (down split rides in gateup launch.)
#define RT_TOK    8
#define RT_BLKS   (T_TOK / RT_TOK)                 // 512
#define XN4       (T_TOK*DIM/4)                    // 524288
#define WPER      (NE*DIM*FDIM/4)                  // 1048576
#define ZERO_BLKS (XN4 / 256)                      // 2048
#define SPL_TOT   (XN4 + 2*WPER)                   // 2621440
#define SPL_BLKS  ((SPL_TOT + 255) / 256)          // 10240

__global__ void __launch_bounds__(256) prep_router_kernel(const float* __restrict__ x,
                                                          const float* __restrict__ rw,
                                                          const float* __restrict__ gw,
                                                          const float* __restrict__ uw,
                                                          float* __restrict__ out) {
    if (blockIdx.x < RT_BLKS) {
        // ---------------- router ----------------
        __shared__ float s_sumP[NE];
        __shared__ float s_zsum;
        __shared__ int   s_cnt[NE];
        __shared__ int   s_base[NE];
        __shared__ int   s_ebuf[NE][2*RT_TOK];
        __shared__ float s_wbuf[NE][2*RT_TOK];

        int tid  = threadIdx.x;
        int wrp  = tid >> 5;
        int lane = tid & 31;
        int tok  = blockIdx.x * RT_TOK + wrp;

        if (tid < NE) { s_sumP[tid] = 0.f; s_cnt[tid] = 0; }
        if (tid == NE) s_zsum = 0.f;
        __syncthreads();

        const float4* xp = (const float4*)(x + (size_t)tok * DIM);
        float4 xv[4];
#pragma unroll
        for (int i = 0; i < 4; i++) xv[i] = xp[lane * 4 + i];

        float logit[NE];
#pragma unroll
        for (int e = 0; e < NE; e++) {
            const float4* wp = (const float4*)(rw + (size_t)e * DIM);
            float acc = 0.f;
#pragma unroll
            for (int i = 0; i < 4; i++) {
                float4 w4 = wp[lane * 4 + i];
                acc += xv[i].x * w4.x + xv[i].y * w4.y + xv[i].z * w4.z + xv[i].w * w4.w;
            }
#pragma unroll
            for (int o = 16; o > 0; o >>= 1) acc += __shfl_xor_sync(0xffffffffu, acc, o);
            logit[e] = acc;
        }

        if (lane == 0) {
            float m = logit[0];
#pragma unroll
            for (int e = 1; e < NE; e++) m = fmaxf(m, logit[e]);
            float p[NE]; float se = 0.f;
#pragma unroll
            for (int e = 0; e < NE; e++) { p[e] = expf(logit[e] - m); se += p[e]; }
            float inv = 1.f / se;

            int i0 = 0; float v0 = -1.f;
#pragma unroll
            for (int e = 0; e < NE; e++) if (p[e] > v0) { v0 = p[e]; i0 = e; }
            int i1 = -1; float v1 = -1.f;
#pragma unroll
            for (int e = 0; e < NE; e++) if (e != i0 && p[e] > v1) { v1 = p[e]; i1 = e; }

            float s2 = v0 + v1;
            float w0 = v0 / s2, w1 = v1 / s2;

            int p0 = atomicAdd(&s_cnt[i0], 1);
            s_ebuf[i0][p0] = (tok << 1);
            s_wbuf[i0][p0] = w0;
            int p1 = atomicAdd(&s_cnt[i1], 1);
            s_ebuf[i1][p1] = (tok << 1) | 1;
            s_wbuf[i1][p1] = w1;

#pragma unroll
            for (int e = 0; e < NE; e++) atomicAdd(&s_sumP[e], p[e] * inv);
            float lse = m + logf(se);
            atomicAdd(&s_zsum, lse * lse);
        }
        __syncthreads();

        if (tid < NE) {
            s_base[tid] = atomicAdd(&g_cnt[tid], s_cnt[tid]);
            atomicAdd(&g_sumP[tid], s_sumP[tid]);
        }
        if (tid == NE) atomicAdd(&g_zsum, s_zsum);
        __syncthreads();

        {
            int e = wrp;
            int c = s_cnt[e], b = s_base[e];
            if (lane < c) {
                g_list[e * T_TOK + b + lane] = s_ebuf[e][lane];
                g_wgt [e * T_TOK + b + lane] = s_wbuf[e][lane];
            }
        }
        return;
    }

    if (blockIdx.x < RT_BLKS + ZERO_BLKS) {
        // ---------------- zero output accumulator region ----------------
        int i = (blockIdx.x - RT_BLKS) * 256 + threadIdx.x;
        ((float4*)out)[i] = make_float4(0.f, 0.f, 0.f, 0.f);
        return;
    }

    // ---------------- split x / gate / up ----------------
    int i = (blockIdx.x - RT_BLKS - ZERO_BLKS) * 256 + threadIdx.x;
    if (i >= SPL_TOT) return;

    const float* src;
    __nv_bfloat16 *oh, *ol;
    size_t j;
    if (i < XN4)            { src = x;  oh = g_xh; ol = g_xl; j = i; }
    else if (i < XN4 + WPER){ src = gw; oh = g_gh; ol = g_gl; j = i - XN4; }
    else                    { src = uw; oh = g_uh; ol = g_ul; j = i - XN4 - WPER; }
    split4_store(((const float4*)src)[j], oh, ol, j);
}

// ================= Phase A: gate/up warp-MMA GEMM (R11 core) + down-weight split slice =================
#define GU_STG  55296
#define GU_SMEM (1024 + 2*GU_STG)
#define GU_GX   16
#define GU_GY   64
#define DSPL_THREADS (GU_GX * GU_GY * 256)   // 262144

__global__ void __launch_bounds__(256, 2) gateup_mma_kernel(const float* __restrict__ dw) {
    // z == NE slice: split the down weights (no consumer until down_mma_kernel)
    if (blockIdx.z == NE) {
        int idx = (blockIdx.y * GU_GX + blockIdx.x) * 256 + threadIdx.x;
        for (int j = idx; j < WPER; j += DSPL_THREADS)
            split4_store(((const float4*)dw)[j], g_dh, g_dl, (size_t)j);
        return;
    }

    extern __shared__ char smem[];
    uint32_t sb = smem_u32(smem);
    int e = blockIdx.z;
    int cnt = g_cnt[e];
    int row0 = blockIdx.y * 64;
    if (row0 >= cnt) return;
    int col0 = blockIdx.x * 64;
    int tid = threadIdx.x, wid = tid >> 5, lid = tid & 31;
    int wm = wid >> 2, wn = wid & 3;
    int g = lid >> 2, t2 = (lid & 3) * 2;
    int* sTok = (int*)smem;

    for (int i = tid; i < 64; i += 256) {
        int r = row0 + i;
        sTok[i] = (r < cnt) ? g_list[e * T_TOK + r] : -1;
    }
    __syncthreads();

    const __nv_bfloat16* b0 = g_gh + (size_t)e * DIM * FDIM;
    const __nv_bfloat16* b1 = g_gl + (size_t)e * DIM * FDIM;
    const __nv_bfloat16* b2 = g_uh + (size_t)e * DIM * FDIM;
    const __nv_bfloat16* b3 = g_ul + (size_t)e * DIM * FDIM;

    float accg[2][2][4] = {}, accu[2][2][4] = {};

    auto stage = [&](int chunk) {
        int kt = chunk * 64;
        uint32_t bb = sb + 1024 + (uint32_t)(chunk & 1) * GU_STG;
#pragma unroll
        for (int it = 0; it < 4; it++) {
            int t = tid + it * 256;
            int arr = t >> 9, u = t & 511, row = u >> 3, seg = u & 7;
            int entry = sTok[row];
            uint32_t bytes = (entry >= 0) ? 16u : 0u;
            const __nv_bfloat16* src = (arr ? g_xl : g_xh)
                + (size_t)((entry >= 0) ? (entry >> 1) : 0) * DIM + kt + seg * 8;
            cp16(bb + arr * 9216 + row * 144 + seg * 16, src, bytes);
        }
#pragma unroll
        for (int it = 0; it < 8; it++) {
            int t = tid + it * 256;
            int arr = t >> 9, u = t & 511, row = u >> 3, seg = u & 7;
            const __nv_bfloat16* src = (arr == 0) ? b0 : (arr == 1) ? b1 : (arr == 2) ? b2 : b3;
            cp16(bb + 18432 + arr * 9216 + row * 144 + seg * 16,
                 src + (size_t)(kt + row) * FDIM + col0 + seg * 8, 16u);
        }
    };

    uint32_t laneO = (uint32_t)(((lid & 7) + ((lid >> 3) & 1) * 8) * 144 + ((lid >> 4) & 1) * 16);

    stage(0); CP_COMMIT();
    for (int c = 0; c < 8; c++) {
        if (c + 1 < 8) { stage(c + 1); CP_COMMIT(); CP_WAITG(1); }
        else           { CP_WAITG(0); }
        __syncthreads();
        uint32_t bb = sb + 1024 + (uint32_t)(c & 1) * GU_STG;
        uint32_t aBase = bb + (uint32_t)(wm * 32) * 144 + laneO;
        uint32_t bBase = bb + 18432 + laneO + (uint32_t)(wn * 16) * 2;
#pragma unroll
        for (int kk = 0; kk < 4; kk++) {
            uint32_t ah[2][4], al[2][4];
#pragma unroll
            for (int mt = 0; mt < 2; mt++) {
                uint32_t aa = aBase + mt * (16 * 144) + kk * 32;
                ldsm_x4(ah[mt], aa);
                ldsm_x4(al[mt], aa + 9216);
            }
            uint32_t ba = bBase + kk * (16 * 144);
            uint32_t bgh[4], bgl[4], buh[4], bul[4];
            ldsm_x4_t(bgh, ba);
            ldsm_x4_t(bgl, ba + 9216);
            ldsm_x4_t(buh, ba + 18432);
            ldsm_x4_t(bul, ba + 27648);
#pragma unroll
            for (int h = 0; h < 2; h++) {
#pragma unroll
                for (int mt = 0; mt < 2; mt++) {
                    mma_bf16(accg[mt][h], ah[mt], bgh + h * 2);
                    mma_bf16(accg[mt][h], ah[mt], bgl + h * 2);
                    mma_bf16(accg[mt][h], al[mt], bgh + h * 2);
                    mma_bf16(accu[mt][h], ah[mt], buh + h * 2);
                    mma_bf16(accu[mt][h], ah[mt], bul + h * 2);
                    mma_bf16(accu[mt][h], al[mt], buh + h * 2);
                }
            }
        }
        __syncthreads();
    }

#pragma unroll
    for (int mt = 0; mt < 2; mt++) {
        int r0 = wm * 32 + mt * 16 + g;
        int e0 = sTok[r0], e1 = sTok[r0 + 8];
#pragma unroll
        for (int h = 0; h < 2; h++) {
            int colg = col0 + wn * 16 + h * 8 + t2;
            const float* dg = accg[mt][h];
            const float* du = accu[mt][h];
            if (e0 >= 0) {
                float h0 = du[0] * (dg[0] / (1.f + expf(-dg[0])));
                float h1 = du[1] * (dg[1] / (1.f + expf(-dg[1])));
                __nv_bfloat16 h0h, h0l, h1h, h1l;
                split_bf16(h0, h0h, h0l); split_bf16(h1, h1h, h1l);
                *(__nv_bfloat162*)(g_hh + (size_t)e0 * FDIM + colg) = __nv_bfloat162(h0h, h1h);
                *(__nv_bfloat162*)(g_hl + (size_t)e0 * FDIM + colg) = __nv_bfloat162(h0l, h1l);
            }
            if (e1 >= 0) {
                float h0 = du[2] * (dg[2] / (1.f + expf(-dg[2])));
                float h1 = du[3] * (dg[3] / (1.f + expf(-dg[3])));
                __nv_bfloat16 h0h, h0l, h1h, h1l;
                split_bf16(h0, h0h, h0l); split_bf16(h1, h1h, h1l);
                *(__nv_bfloat162*)(g_hh + (size_t)e1 * FDIM + colg) = __nv_bfloat162(h0h, h1h);
                *(__nv_bfloat162*)(g_hl + (size_t)e1 * FDIM + colg) = __nv_bfloat162(h0l, h1l);
            }
        }
    }
}

// ================= Phase B: down warp-MMA GEMM (R11 core) — atomic epilogue into out =================
#define DN_STG  36864
#define DN_SMEM (1024 + 2*DN_STG)

__global__ void __launch_bounds__(256, 3) down_mma_kernel(float* __restrict__ out, int out_size) {
    // aux loss from block (0,0,0) (g_cnt/g_sumP/g_zsum final since router launch ended)
    if (blockIdx.x == 0 && blockIdx.y == 0 && blockIdx.z == 0 && threadIdx.x == 0) {
        float lb = 0.f;
#pragma unroll
        for (int e = 0; e < NE; e++)
            lb += ((float)g_cnt[e] / (float)NPAIR) * (g_sumP[e] / (float)T_TOK);
        out[out_size - 1] = 0.01f * (float)NE * lb + 0.001f * (g_zsum / (float)T_TOK);
    }

    extern __shared__ char smem[];
    uint32_t sb = smem_u32(smem);
    int e = blockIdx.z;
    int cnt = g_cnt[e];
    int row0 = blockIdx.y * 64;
    if (row0 >= cnt) return;
    int col0 = blockIdx.x * 64;
    int tid = threadIdx.x, wid = tid >> 5, lid = tid & 31;
    int wm = wid >> 2, wn = wid & 3;
    int g = lid >> 2, t2 = (lid & 3) * 2;
    int*   sTok = (int*)smem;
    float* sW   = (float*)(smem + 256);

    for (int i = tid; i < 64; i += 256) {
        int r = row0 + i;
        sTok[i] = (r < cnt) ? g_list[e * T_TOK + r] : -1;
        sW[i]   = (r < cnt) ? g_wgt [e * T_TOK + r] : 0.f;
    }
    __syncthreads();

    const __nv_bfloat16* dh = g_dh + (size_t)e * FDIM * DIM;
    const __nv_bfloat16* dl = g_dl + (size_t)e * FDIM * DIM;

    float acc[2][2][4] = {};

    auto stage = [&](int chunk) {
        int kt = chunk * 64;
        uint32_t bb = sb + 1024 + (uint32_t)(chunk & 1) * DN_STG;
#pragma unroll
        for (int it = 0; it < 4; it++) {
            int t = tid + it * 256;
            int arr = t >> 9, u = t & 511, row = u >> 3, seg = u & 7;
            int entry = sTok[row];
            uint32_t bytes = (entry >= 0) ? 16u : 0u;
            const __nv_bfloat16* src = (arr ? g_hl : g_hh)
                + (size_t)((entry >= 0) ? entry : 0) * FDIM + kt + seg * 8;
            cp16(bb + arr * 9216 + row * 144 + seg * 16, src, bytes);
        }
#pragma unroll
        for (int it = 0; it < 4; it++) {
            int t = tid + it * 256;
            int arr = t >> 9, u = t & 511, row = u >> 3, seg = u & 7;
            const __nv_bfloat16* src = (arr ? dl : dh)
                + (size_t)(kt + row) * DIM + col0 + seg * 8;
            cp16(bb + 18432 + arr * 9216 + row * 144 + seg * 16, src, 16u);
        }
    };

    uint32_t laneO = (uint32_t)(((lid & 7) + ((lid >> 3) & 1) * 8) * 144 + ((lid >> 4) & 1) * 16);

    stage(0); CP_COMMIT();
    for (int c = 0; c < 16; c++) {
        if (c + 1 < 16) { stage(c + 1); CP_COMMIT(); CP_WAITG(1); }
        else            { CP_WAITG(0); }
        __syncthreads();
        uint32_t bb = sb + 1024 + (uint32_t)(c & 1) * DN_STG;
        uint32_t aBase = bb + (uint32_t)(wm * 32) * 144 + laneO;
        uint32_t bBase = bb + 18432 + laneO + (uint32_t)(wn * 16) * 2;
#pragma unroll
        for (int kk = 0; kk < 4; kk++) {
            uint32_t ah[2][4], al[2][4];
#pragma unroll
            for (int mt = 0; mt < 2; mt++) {
                uint32_t aa = aBase + mt * (16 * 144) + kk * 32;
                ldsm_x4(ah[mt], aa);
                ldsm_x4(al[mt], aa + 9216);
            }
            uint32_t ba = bBase + kk * (16 * 144);
            uint32_t bh[4], bl[4];
            ldsm_x4_t(bh, ba);
            ldsm_x4_t(bl, ba + 9216);
#pragma unroll
            for (int h = 0; h < 2; h++) {
#pragma unroll
                for (int mt = 0; mt < 2; mt++) {
                    mma_bf16(acc[mt][h], ah[mt], bh + h * 2);
                    mma_bf16(acc[mt][h], ah[mt], bl + h * 2);
                    mma_bf16(acc[mt][h], al[mt], bh + h * 2);
                }
            }
        }
        __syncthreads();
    }

    // epilogue: scale by combine weight, atomicAdd into out (exactly 2 adds per element)
#pragma unroll
    for (int mt = 0; mt < 2; mt++) {
        int r0 = wm * 32 + mt * 16 + g;
        int e0 = sTok[r0], e1 = sTok[r0 + 8];
        float w0 = sW[r0], w1 = sW[r0 + 8];
#pragma unroll
        for (int h = 0; h < 2; h++) {
            int cg = col0 + wn * 16 + h * 8 + t2;
            const float* d = acc[mt][h];
            if (e0 >= 0) {
                float* op = out + (size_t)(e0 >> 1) * DIM + cg;
                atomicAdd(op,     w0 * d[0]);
                atomicAdd(op + 1, w0 * d[1]);
            }
            if (e1 >= 0) {
                float* op = out + (size_t)(e1 >> 1) * DIM + cg;
                atomicAdd(op,     w1 * d[2]);
                atomicAdd(op + 1, w1 * d[3]);
            }
        }
    }
}

// ---------------- reset accumulators for the next launch (graph replay) ----------------
__global__ void reset_kernel() {
    int i = threadIdx.x;
    if (i < NE) { g_cnt[i] = 0; g_sumP[i] = 0.f; }
    if (i == 0) g_zsum = 0.f;
}

// ---------------- launch ----------------
extern "C" void kernel_launch(void* const* d_in, const int* in_sizes, int n_in,
                              void* d_out, int out_size) {
    const float* x  = (const float*)d_in[0];
    const float* rw = (const float*)d_in[1];
    const float* gw = (const float*)d_in[2];
    const float* uw = (const float*)d_in[3];
    const float* dw = (const float*)d_in[4];
    float* out = (float*)d_out;

    cudaFuncSetAttribute(gateup_mma_kernel, cudaFuncAttributeMaxDynamicSharedMemorySize, GU_SMEM);
    cudaFuncSetAttribute(down_mma_kernel,   cudaFuncAttributeMaxDynamicSharedMemorySize, DN_SMEM);

    prep_router_kernel<<<RT_BLKS + ZERO_BLKS + SPL_BLKS, 256>>>(x, rw, gw, uw, out);
    gateup_mma_kernel<<<dim3(GU_GX, GU_GY, NE + 1), 256, GU_SMEM>>>(dw);
    down_mma_kernel<<<dim3(DIM / 64, T_TOK / 64, NE), 256, DN_SMEM>>>(out, out_size);
    reset_kernel<<<1, 32>>>();
}

// round 16
// speedup vs baseline: 1.3203x; 1.2319x over previous
#include <cuda_runtime.h>
#include <cuda_fp16.h>
#include <math.h>
#include <stdint.h>

// Problem constants (fixed shapes)
#define T_TOK 4096
#define DIM   512
#define FDIM  1024
#define NE    8
#define TOPK  2
#define NPAIR (T_TOK*TOPK)

// ---------------- device scratch (static; no runtime allocation) ----------------
// INVARIANT: g_cnt/g_sumP/g_zsum are zero at kernel_launch entry.
__device__ int   g_cnt[NE];
__device__ int   g_list[NE*T_TOK];   // packed (token<<1)|k
__device__ float g_wgt [NE*T_TOK];
__device__ float g_sumP[NE];
__device__ float g_zsum;

// fp16 operands: x single-rounded; gate/up hi/lo; down single; hidden hi/lo.
__device__ __half g_x  [(size_t)T_TOK*DIM];
__device__ __half g_gh [(size_t)NE*DIM*FDIM];   // gate hi [E][D][F]
__device__ __half g_gl [(size_t)NE*DIM*FDIM];   // gate lo
__device__ __half g_uh [(size_t)NE*DIM*FDIM];   // up hi
__device__ __half g_ul [(size_t)NE*DIM*FDIM];   // up lo
__device__ __half g_d  [(size_t)NE*FDIM*DIM];   // down single [E][F][D]
__device__ __half g_hh [(size_t)NPAIR*FDIM];    // hidden hi
__device__ __half g_hl [(size_t)NPAIR*FDIM];    // hidden lo

// ================= PTX helpers (family-portable: sm_80+) =================
__device__ __forceinline__ uint32_t smem_u32(const void* p) {
    uint32_t a;
    asm("{ .reg .u64 t; cvta.to.shared.u64 t, %1; cvt.u32.u64 %0, t; }" : "=r"(a) : "l"(p));
    return a;
}
__device__ __forceinline__ void cp16(uint32_t dst, const void* src, uint32_t bytes) {
    asm volatile("cp.async.cg.shared.global [%0], [%1], 16, %2;"
                 :: "r"(dst), "l"(src), "r"(bytes) : "memory");
}
#define CP_COMMIT() asm volatile("cp.async.commit_group;" ::: "memory")
#define CP_WAITG(n) asm volatile("cp.async.wait_group %0;" :: "n"(n) : "memory")

__device__ __forceinline__ void ldsm_x4(uint32_t* r, uint32_t addr) {
    asm volatile("ldmatrix.sync.aligned.m8n8.x4.shared.b16 {%0,%1,%2,%3}, [%4];"
        : "=r"(r[0]), "=r"(r[1]), "=r"(r[2]), "=r"(r[3]) : "r"(addr));
}
__device__ __forceinline__ void ldsm_x4_t(uint32_t* r, uint32_t addr) {
    asm volatile("ldmatrix.sync.aligned.m8n8.x4.trans.shared.b16 {%0,%1,%2,%3}, [%4];"
        : "=r"(r[0]), "=r"(r[1]), "=r"(r[2]), "=r"(r[3]) : "r"(addr));
}
__device__ __forceinline__ void mma_f16(float* d, const uint32_t* a, const uint32_t* b) {
    asm volatile("mma.sync.aligned.m16n8k16.row.col.f32.f16.f16.f32 "
        "{%0,%1,%2,%3}, {%4,%5,%6,%7}, {%8,%9}, {%0,%1,%2,%3};"
        : "+f"(d[0]), "+f"(d[1]), "+f"(d[2]), "+f"(d[3])
        : "r"(a[0]), "r"(a[1]), "r"(a[2]), "r"(a[3]), "r"(b[0]), "r"(b[1]));
}

__device__ __forceinline__ void split_h(float v, __half& h, __half& l) {
    h = __float2half(v);
    l = __float2half(v - __half2float(h));
}
// store 4 floats as single-rounded fp16
__device__ __forceinline__ void cvt4_store(const float4 v, __half* o, size_t j) {
    ((__half2*)o)[2*j]   = __floats2half2_rn(v.x, v.y);
    ((__half2*)o)[2*j+1] = __floats2half2_rn(v.z, v.w);
}
// store 4 floats as fp16 hi/lo pair
__device__ __forceinline__ void split4_store(const float4 v, __half* oh, __half* ol, size_t j) {
    __half h0,h1,h2,h3,l0,l1,l2,l3;
    split_h(v.x,h0,l0); split_h(v.y,h1,l1);
    split_h(v.z,h2,l2); split_h(v.w,h3,l3);
    ((__half2*)oh)[2*j]   = __halves2half2(h0,h1);
    ((__half2*)oh)[2*j+1] = __halves2half2(h2,h3);
    ((__half2*)ol)[2*j]   = __halves2half2(l0,l1);
    ((__half2*)ol)[2*j+1] = __halves2half2(l2,l3);
}

// ---------------- fused router + out-zero + x/gate/up conversion (one launch) ----------------
#define RT_TOK    8
#define RT_BLKS   (T_TOK / RT_TOK)                 // 512
#define XN4       (T_TOK*DIM/4)                    // 524288
#define WPER      (NE*DIM*FDIM/4)                  // 1048576
#define ZERO_BLKS (XN4 / 256)                      // 2048
#define SPL_TOT   (XN4 + 2*WPER)                   // 2621440
#define SPL_BLKS  ((SPL_TOT + 255) / 256)          // 10240

__global__ void __launch_bounds__(256) prep_router_kernel(const float* __restrict__ x,
                                                          const float* __restrict__ rw,
                                                          const float* __restrict__ gw,
                                                          const float* __restrict__ uw,
                                                          float* __restrict__ out) {
    if (blockIdx.x < RT_BLKS) {
        // ---------------- router ----------------
        __shared__ float s_sumP[NE];
        __shared__ float s_zsum;
        __shared__ int   s_cnt[NE];
        __shared__ int   s_base[NE];
        __shared__ int   s_ebuf[NE][2*RT_TOK];
        __shared__ float s_wbuf[NE][2*RT_TOK];

        int tid  = threadIdx.x;
        int wrp  = tid >> 5;
        int lane = tid & 31;
        int tok  = blockIdx.x * RT_TOK + wrp;

        if (tid < NE) { s_sumP[tid] = 0.f; s_cnt[tid] = 0; }
        if (tid == NE) s_zsum = 0.f;
        __syncthreads();

        const float4* xp = (const float4*)(x + (size_t)tok * DIM);
        float4 xv[4];
#pragma unroll
        for (int i = 0; i < 4; i++) xv[i] = xp[lane * 4 + i];

        float logit[NE];
#pragma unroll
        for (int e = 0; e < NE; e++) {
            const float4* wp = (const float4*)(rw + (size_t)e * DIM);
            float acc = 0.f;
#pragma unroll
            for (int i = 0; i < 4; i++) {
                float4 w4 = wp[lane * 4 + i];
                acc += xv[i].x * w4.x + xv[i].y * w4.y + xv[i].z * w4.z + xv[i].w * w4.w;
            }
#pragma unroll
            for (int o = 16; o > 0; o >>= 1) acc += __shfl_xor_sync(0xffffffffu, acc, o);
            logit[e] = acc;
        }

        if (lane == 0) {
            float m = logit[0];
#pragma unroll
            for (int e = 1; e < NE; e++) m = fmaxf(m, logit[e]);
            float p[NE]; float se = 0.f;
#pragma unroll
            for (int e = 0; e < NE; e++) { p[e] = expf(logit[e] - m); se += p[e]; }
            float inv = 1.f / se;

            int i0 = 0; float v0 = -1.f;
#pragma unroll
            for (int e = 0; e < NE; e++) if (p[e] > v0) { v0 = p[e]; i0 = e; }
            int i1 = -1; float v1 = -1.f;
#pragma unroll
            for (int e = 0; e < NE; e++) if (e != i0 && p[e] > v1) { v1 = p[e]; i1 = e; }

            float s2 = v0 + v1;
            float w0 = v0 / s2, w1 = v1 / s2;

            int p0 = atomicAdd(&s_cnt[i0], 1);
            s_ebuf[i0][p0] = (tok << 1);
            s_wbuf[i0][p0] = w0;
            int p1 = atomicAdd(&s_cnt[i1], 1);
            s_ebuf[i1][p1] = (tok << 1) | 1;
            s_wbuf[i1][p1] = w1;

#pragma unroll
            for (int e = 0; e < NE; e++) atomicAdd(&s_sumP[e], p[e] * inv);
            float lse = m + logf(se);
            atomicAdd(&s_zsum, lse * lse);
        }
        __syncthreads();

        if (tid < NE) {
            s_base[tid] = atomicAdd(&g_cnt[tid], s_cnt[tid]);
            atomicAdd(&g_sumP[tid], s_sumP[tid]);
        }
        if (tid == NE) atomicAdd(&g_zsum, s_zsum);
        __syncthreads();

        {
            int e = wrp;
            int c = s_cnt[e], b = s_base[e];
            if (lane < c) {
                g_list[e * T_TOK + b + lane] = s_ebuf[e][lane];
                g_wgt [e * T_TOK + b + lane] = s_wbuf[e][lane];
            }
        }
        return;
    }

    if (blockIdx.x < RT_BLKS + ZERO_BLKS) {
        int i = (blockIdx.x - RT_BLKS) * 256 + threadIdx.x;
        ((float4*)out)[i] = make_float4(0.f, 0.f, 0.f, 0.f);
        return;
    }

    // convert x (single) / gate (hi/lo) / up (hi/lo)
    int i = (blockIdx.x - RT_BLKS - ZERO_BLKS) * 256 + threadIdx.x;
    if (i >= SPL_TOT) return;

    if (i < XN4) {
        cvt4_store(((const float4*)x)[i], g_x, (size_t)i);
    } else if (i < XN4 + WPER) {
        size_t j = i - XN4;
        split4_store(((const float4*)gw)[j], g_gh, g_gl, j);
    } else {
        size_t j = i - XN4 - WPER;
        split4_store(((const float4*)uw)[j], g_uh, g_ul, j);
    }
}

// ================= Phase A: gate/up fp16 warp-MMA GEMM + down-weight convert slice =================
// Block tile M=64 x N=64, K chunks of 64 (8 chunks), 2-stage pipeline, 2 blocks/SM.
// Stage: A 9216 (single), B at 9216: gh, gl, uh, ul (9216 each). Stage = 46080.
#define GU_STG  46080
#define GU_SMEM (1024 + 2*GU_STG)
#define GU_GX   16
#define GU_GY   64
#define DSPL_THREADS (GU_GX * GU_GY * 256)   // 262144

__global__ void __launch_bounds__(256, 2) gateup_mma_kernel(const float* __restrict__ dw) {
    // z == NE slice: convert down weights to single fp16
    if (blockIdx.z == NE) {
        int idx = (blockIdx.y * GU_GX + blockIdx.x) * 256 + threadIdx.x;
        for (int j = idx; j < WPER; j += DSPL_THREADS)
            cvt4_store(((const float4*)dw)[j], g_d, (size_t)j);
        return;
    }

    extern __shared__ char smem[];
    uint32_t sb = smem_u32(smem);
    int e = blockIdx.z;
    int cnt = g_cnt[e];
    int row0 = blockIdx.y * 64;
    if (row0 >= cnt) return;
    int col0 = blockIdx.x * 64;
    int tid = threadIdx.x, wid = tid >> 5, lid = tid & 31;
    int wm = wid >> 2, wn = wid & 3;
    int g = lid >> 2, t2 = (lid & 3) * 2;
    int* sTok = (int*)smem;

    for (int i = tid; i < 64; i += 256) {
        int r = row0 + i;
        sTok[i] = (r < cnt) ? g_list[e * T_TOK + r] : -1;
    }
    __syncthreads();

    const __half* b0 = g_gh + (size_t)e * DIM * FDIM;
    const __half* b1 = g_gl + (size_t)e * DIM * FDIM;
    const __half* b2 = g_uh + (size_t)e * DIM * FDIM;
    const __half* b3 = g_ul + (size_t)e * DIM * FDIM;

    float accg[2][2][4] = {}, accu[2][2][4] = {};

    auto stage = [&](int chunk) {
        int kt = chunk * 64;
        uint32_t bb = sb + 1024 + (uint32_t)(chunk & 1) * GU_STG;
        // A (single) gathered: 512 cp16
#pragma unroll
        for (int it = 0; it < 2; it++) {
            int t = tid + it * 256;
            int row = t >> 3, seg = t & 7;
            int entry = sTok[row];
            uint32_t bytes = (entry >= 0) ? 16u : 0u;
            const __half* src = g_x
                + (size_t)((entry >= 0) ? (entry >> 1) : 0) * DIM + kt + seg * 8;
            cp16(bb + row * 144 + seg * 16, src, bytes);
        }
        // B 4 arrays: 2048 cp16
#pragma unroll
        for (int it = 0; it < 8; it++) {
            int t = tid + it * 256;
            int arr = t >> 9, u = t & 511, row = u >> 3, seg = u & 7;
            const __half* src = (arr == 0) ? b0 : (arr == 1) ? b1 : (arr == 2) ? b2 : b3;
            cp16(bb + 9216 + arr * 9216 + row * 144 + seg * 16,
                 src + (size_t)(kt + row) * FDIM + col0 + seg * 8, 16u);
        }
    };

    uint32_t laneO = (uint32_t)(((lid & 7) + ((lid >> 3) & 1) * 8) * 144 + ((lid >> 4) & 1) * 16);

    stage(0); CP_COMMIT();
    for (int c = 0; c < 8; c++) {
        if (c + 1 < 8) { stage(c + 1); CP_COMMIT(); CP_WAITG(1); }
        else           { CP_WAITG(0); }
        __syncthreads();
        uint32_t bb = sb + 1024 + (uint32_t)(c & 1) * GU_STG;
        uint32_t aBase = bb + (uint32_t)(wm * 32) * 144 + laneO;
        uint32_t bBase = bb + 9216 + laneO + (uint32_t)(wn * 16) * 2;
#pragma unroll
        for (int kk = 0; kk < 4; kk++) {
            uint32_t ah[2][4];
#pragma unroll
            for (int mt = 0; mt < 2; mt++)
                ldsm_x4(ah[mt], aBase + mt * (16 * 144) + kk * 32);
            uint32_t ba = bBase + kk * (16 * 144);
            uint32_t bgh[4], bgl[4], buh[4], bul[4];
            ldsm_x4_t(bgh, ba);
            ldsm_x4_t(bgl, ba + 9216);
            ldsm_x4_t(buh, ba + 18432);
            ldsm_x4_t(bul, ba + 27648);
#pragma unroll
            for (int h = 0; h < 2; h++) {
#pragma unroll
                for (int mt = 0; mt < 2; mt++) {
                    mma_f16(accg[mt][h], ah[mt], bgh + h * 2);
                    mma_f16(accg[mt][h], ah[mt], bgl + h * 2);
                    mma_f16(accu[mt][h], ah[mt], buh + h * 2);
                    mma_f16(accu[mt][h], ah[mt], bul + h * 2);
                }
            }
        }
        __syncthreads();
    }

    // epilogue: h = silu(gate)*up, split to fp16 hi/lo
#pragma unroll
    for (int mt = 0; mt < 2; mt++) {
        int r0 = wm * 32 + mt * 16 + g;
        int e0 = sTok[r0], e1 = sTok[r0 + 8];
#pragma unroll
        for (int h = 0; h < 2; h++) {
            int colg = col0 + wn * 16 + h * 8 + t2;
            const float* dg = accg[mt][h];
            const float* du = accu[mt][h];
            if (e0 >= 0) {
                float h0 = du[0] * (dg[0] / (1.f + expf(-dg[0])));
                float h1 = du[1] * (dg[1] / (1.f + expf(-dg[1])));
                __half h0h, h0l, h1h, h1l;
                split_h(h0, h0h, h0l); split_h(h1, h1h, h1l);
                *(__half2*)(g_hh + (size_t)e0 * FDIM + colg) = __halves2half2(h0h, h1h);
                *(__half2*)(g_hl + (size_t)e0 * FDIM + colg) = __halves2half2(h0l, h1l);
            }
            if (e1 >= 0) {
                float h0 = du[2] * (dg[2] / (1.f + expf(-dg[2])));
                float h1 = du[3] * (dg[3] / (1.f + expf(-dg[3])));
                __half h0h, h0l, h1h, h1l;
                split_h(h0, h0h, h0l); split_h(h1, h1h, h1l);
                *(__half2*)(g_hh + (size_t)e1 * FDIM + colg) = __halves2half2(h0h, h1h);
                *(__half2*)(g_hl + (size_t)e1 * FDIM + colg) = __halves2half2(h0l, h1l);
            }
        }
    }
}

// ================= Phase B: down fp16 warp-MMA GEMM — atomic epilogue into out =================
// Block tile M=64 x N=64, K=1024 in 16 chunks, 2-stage pipeline, 3 blocks/SM.
// Stage: A hh 0, hl 9216; B (single) 18432. Stage = 27648.
#define DN_STG  27648
#define DN_SMEM (1024 + 2*DN_STG)

__global__ void __launch_bounds__(256, 3) down_mma_kernel(float* __restrict__ out, int out_size) {
    if (blockIdx.x == 0 && blockIdx.y == 0 && blockIdx.z == 0 && threadIdx.x == 0) {
        float lb = 0.f;
#pragma unroll
        for (int e = 0; e < NE; e++)
            lb += ((float)g_cnt[e] / (float)NPAIR) * (g_sumP[e] / (float)T_TOK);
        out[out_size - 1] = 0.01f * (float)NE * lb + 0.001f * (g_zsum / (float)T_TOK);
    }

    extern __shared__ char smem[];
    uint32_t sb = smem_u32(smem);
    int e = blockIdx.z;
    int cnt = g_cnt[e];
    int row0 = blockIdx.y * 64;
    if (row0 >= cnt) return;
    int col0 = blockIdx.x * 64;
    int tid = threadIdx.x, wid = tid >> 5, lid = tid & 31;
    int wm = wid >> 2, wn = wid & 3;
    int g = lid >> 2, t2 = (lid & 3) * 2;
    int*   sTok = (int*)smem;
    float* sW   = (float*)(smem + 256);

    for (int i = tid; i < 64; i += 256) {
        int r = row0 + i;
        sTok[i] = (r < cnt) ? g_list[e * T_TOK + r] : -1;
        sW[i]   = (r < cnt) ? g_wgt [e * T_TOK + r] : 0.f;
    }
    __syncthreads();

    const __half* dwp = g_d + (size_t)e * FDIM * DIM;

    float acc[2][2][4] = {};

    auto stage = [&](int chunk) {
        int kt = chunk * 64;
        uint32_t bb = sb + 1024 + (uint32_t)(chunk & 1) * DN_STG;
        // A hidden hi/lo gathered: 1024 cp16
#pragma unroll
        for (int it = 0; it < 4; it++) {
            int t = tid + it * 256;
            int arr = t >> 9, u = t & 511, row = u >> 3, seg = u & 7;
            int entry = sTok[row];
            uint32_t bytes = (entry >= 0) ? 16u : 0u;
            const __half* src = (arr ? g_hl : g_hh)
                + (size_t)((entry >= 0) ? entry : 0) * FDIM + kt + seg * 8;
            cp16(bb + arr * 9216 + row * 144 + seg * 16, src, bytes);
        }
        // B (single): 512 cp16
#pragma unroll
        for (int it = 0; it < 2; it++) {
            int t = tid + it * 256;
            int row = t >> 3, seg = t & 7;
            const __half* src = dwp + (size_t)(kt + row) * DIM + col0 + seg * 8;
            cp16(bb + 18432 + row * 144 + seg * 16, src, 16u);
        }
    };

    uint32_t laneO = (uint32_t)(((lid & 7) + ((lid >> 3) & 1) * 8) * 144 + ((lid >> 4) & 1) * 16);

    stage(0); CP_COMMIT();
    for (int c = 0; c < 16; c++) {
        if (c + 1 < 16) { stage(c + 1); CP_COMMIT(); CP_WAITG(1); }
        else            { CP_WAITG(0); }
        __syncthreads();
        uint32_t bb = sb + 1024 + (uint32_t)(c & 1) * DN_STG;
        uint32_t aBase = bb + (uint32_t)(wm * 32) * 144 + laneO;
        uint32_t bBase = bb + 18432 + laneO + (uint32_t)(wn * 16) * 2;
#pragma unroll
        for (int kk = 0; kk < 4; kk++) {
            uint32_t ah[2][4], al[2][4];
#pragma unroll
            for (int mt = 0; mt < 2; mt++) {
                uint32_t aa = aBase + mt * (16 * 144) + kk * 32;
                ldsm_x4(ah[mt], aa);
                ldsm_x4(al[mt], aa + 9216);
            }
            uint32_t bh[4];
            ldsm_x4_t(bh, bBase + kk * (16 * 144));
#pragma unroll
            for (int h = 0; h < 2; h++) {
#pragma unroll
                for (int mt = 0; mt < 2; mt++) {
                    mma_f16(acc[mt][h], ah[mt], bh + h * 2);
                    mma_f16(acc[mt][h], al[mt], bh + h * 2);
                }
            }
        }
        __syncthreads();
    }

    // epilogue: scale by combine weight, atomicAdd into out (exactly 2 adds per element)
#pragma unroll
    for (int mt = 0; mt < 2; mt++) {
        int r0 = wm * 32 + mt * 16 + g;
        int e0 = sTok[r0], e1 = sTok[r0 + 8];
        float w0 = sW[r0], w1 = sW[r0 + 8];
#pragma unroll
        for (int h = 0; h < 2; h++) {
            int cg = col0 + wn * 16 + h * 8 + t2;
            const float* d = acc[mt][h];
            if (e0 >= 0) {
                float* op = out + (size_t)(e0 >> 1) * DIM + cg;
                atomicAdd(op,     w0 * d[0]);
                atomicAdd(op + 1, w0 * d[1]);
            }
            if (e1 >= 0) {
                float* op = out + (size_t)(e1 >> 1) * DIM + cg;
                atomicAdd(op,     w1 * d[2]);
                atomicAdd(op + 1, w1 * d[3]);
            }
        }
    }
}

// ---------------- reset accumulators for the next launch (graph replay) ----------------
__global__ void reset_kernel() {
    int i = threadIdx.x;
    if (i < NE) { g_cnt[i] = 0; g_sumP[i] = 0.f; }
    if (i == 0) g_zsum = 0.f;
}

// ---------------- launch ----------------
extern "C" void kernel_launch(void* const* d_in, const int* in_sizes, int n_in,
                              void* d_out, int out_size) {
    const float* x  = (const float*)d_in[0];
    const float* rw = (const float*)d_in[1];
    const float* gw = (const float*)d_in[2];
    const float* uw = (const float*)d_in[3];
    const float* dw = (const float*)d_in[4];
    float* out = (float*)d_out;

    cudaFuncSetAttribute(gateup_mma_kernel, cudaFuncAttributeMaxDynamicSharedMemorySize, GU_SMEM);
    cudaFuncSetAttribute(down_mma_kernel,   cudaFuncAttributeMaxDynamicSharedMemorySize, DN_SMEM);

    prep_router_kernel<<<RT_BLKS + ZERO_BLKS + SPL_BLKS, 256>>>(x, rw, gw, uw, out);
    gateup_mma_kernel<<<dim3(GU_GX, GU_GY, NE + 1), 256, GU_SMEM>>>(dw);
    down_mma_kernel<<<dim3(DIM / 64, T_TOK / 64, NE), 256, DN_SMEM>>>(out, out_size);
    reset_kernel<<<1, 32>>>();
}

// round 17
// speedup vs baseline: 2.0302x; 1.5377x over previous
#include <cuda_runtime.h>
#include <cuda_fp16.h>
#include <math.h>
#include <stdint.h>

// Problem constants (fixed shapes)
#define T_TOK 4096
#define DIM   512
#define FDIM  1024
#define NE    8
#define TOPK  2
#define NPAIR (T_TOK*TOPK)

// ---------------- device scratch (static; no runtime allocation) ----------------
// INVARIANT: g_cnt/g_sumP/g_zsum are zero at kernel_launch entry.
__device__ int   g_cnt[NE];
__device__ int   g_list[NE*T_TOK];   // packed (token<<1)|k
__device__ float g_wgt [NE*T_TOK];
__device__ float g_sumP[NE];
__device__ float g_zsum;

// single-rounded fp16 operands
__device__ __half g_x [(size_t)T_TOK*DIM];
__device__ __half g_g [(size_t)NE*DIM*FDIM];   // gate [E][D][F]
__device__ __half g_u [(size_t)NE*DIM*FDIM];   // up   [E][D][F]
__device__ __half g_d [(size_t)NE*FDIM*DIM];   // down [E][F][D]
__device__ __half g_h [(size_t)NPAIR*FDIM];    // hidden

// ================= PTX helpers (family-portable: sm_80+) =================
__device__ __forceinline__ uint32_t smem_u32(const void* p) {
    uint32_t a;
    asm("{ .reg .u64 t; cvta.to.shared.u64 t, %1; cvt.u32.u64 %0, t; }" : "=r"(a) : "l"(p));
    return a;
}
__device__ __forceinline__ void cp16(uint32_t dst, const void* src, uint32_t bytes) {
    asm volatile("cp.async.cg.shared.global [%0], [%1], 16, %2;"
                 :: "r"(dst), "l"(src), "r"(bytes) : "memory");
}
#define CP_COMMIT() asm volatile("cp.async.commit_group;" ::: "memory")
#define CP_WAITG(n) asm volatile("cp.async.wait_group %0;" :: "n"(n) : "memory")

__device__ __forceinline__ void ldsm_x4(uint32_t* r, uint32_t addr) {
    asm volatile("ldmatrix.sync.aligned.m8n8.x4.shared.b16 {%0,%1,%2,%3}, [%4];"
        : "=r"(r[0]), "=r"(r[1]), "=r"(r[2]), "=r"(r[3]) : "r"(addr));
}
__device__ __forceinline__ void ldsm_x4_t(uint32_t* r, uint32_t addr) {
    asm volatile("ldmatrix.sync.aligned.m8n8.x4.trans.shared.b16 {%0,%1,%2,%3}, [%4];"
        : "=r"(r[0]), "=r"(r[1]), "=r"(r[2]), "=r"(r[3]) : "r"(addr));
}
__device__ __forceinline__ void mma_f16(float* d, const uint32_t* a, const uint32_t* b) {
    asm volatile("mma.sync.aligned.m16n8k16.row.col.f32.f16.f16.f32 "
        "{%0,%1,%2,%3}, {%4,%5,%6,%7}, {%8,%9}, {%0,%1,%2,%3};"
        : "+f"(d[0]), "+f"(d[1]), "+f"(d[2]), "+f"(d[3])
        : "r"(a[0]), "r"(a[1]), "r"(a[2]), "r"(a[3]), "r"(b[0]), "r"(b[1]));
}

// store 4 floats as single-rounded fp16
__device__ __forceinline__ void cvt4_store(const float4 v, __half* o, size_t j) {
    ((__half2*)o)[2*j]   = __floats2half2_rn(v.x, v.y);
    ((__half2*)o)[2*j+1] = __floats2half2_rn(v.z, v.w);
}

// ---------------- fused router + out-zero + x/gate/up conversion (one launch) ----------------
#define RT_TOK    8
#define RT_BLKS   (T_TOK / RT_TOK)                 // 512
#define XN4       (T_TOK*DIM/4)                    // 524288
#define WPER      (NE*DIM*FDIM/4)                  // 1048576
#define ZERO_BLKS (XN4 / 256)                      // 2048
#define SPL_TOT   (XN4 + 2*WPER)                   // 2621440
#define SPL_BLKS  ((SPL_TOT + 255) / 256)          // 10240

__global__ void __launch_bounds__(256) prep_router_kernel(const float* __restrict__ x,
                                                          const float* __restrict__ rw,
                                                          const float* __restrict__ gw,
                                                          const float* __restrict__ uw,
                                                          float* __restrict__ out) {
    if (blockIdx.x < RT_BLKS) {
        // ---------------- router ----------------
        __shared__ float s_sumP[NE];
        __shared__ float s_zsum;
        __shared__ int   s_cnt[NE];
        __shared__ int   s_base[NE];
        __shared__ int   s_ebuf[NE][2*RT_TOK];
        __shared__ float s_wbuf[NE][2*RT_TOK];

        int tid  = threadIdx.x;
        int wrp  = tid >> 5;
        int lane = tid & 31;
        int tok  = blockIdx.x * RT_TOK + wrp;

        if (tid < NE) { s_sumP[tid] = 0.f; s_cnt[tid] = 0; }
        if (tid == NE) s_zsum = 0.f;
        __syncthreads();

        const float4* xp = (const float4*)(x + (size_t)tok * DIM);
        float4 xv[4];
#pragma unroll
        for (int i = 0; i < 4; i++) xv[i] = xp[lane * 4 + i];

        float logit[NE];
#pragma unroll
        for (int e = 0; e < NE; e++) {
            const float4* wp = (const float4*)(rw + (size_t)e * DIM);
            float acc = 0.f;
#pragma unroll
            for (int i = 0; i < 4; i++) {
                float4 w4 = wp[lane * 4 + i];
                acc += xv[i].x * w4.x + xv[i].y * w4.y + xv[i].z * w4.z + xv[i].w * w4.w;
            }
#pragma unroll
            for (int o = 16; o > 0; o >>= 1) acc += __shfl_xor_sync(0xffffffffu, acc, o);
            logit[e] = acc;
        }

        if (lane == 0) {
            float m = logit[0];
#pragma unroll
            for (int e = 1; e < NE; e++) m = fmaxf(m, logit[e]);
            float p[NE]; float se = 0.f;
#pragma unroll
            for (int e = 0; e < NE; e++) { p[e] = expf(logit[e] - m); se += p[e]; }
            float inv = 1.f / se;

            int i0 = 0; float v0 = -1.f;
#pragma unroll
            for (int e = 0; e < NE; e++) if (p[e] > v0) { v0 = p[e]; i0 = e; }
            int i1 = -1; float v1 = -1.f;
#pragma unroll
            for (int e = 0; e < NE; e++) if (e != i0 && p[e] > v1) { v1 = p[e]; i1 = e; }

            float s2 = v0 + v1;
            float w0 = v0 / s2, w1 = v1 / s2;

            int p0 = atomicAdd(&s_cnt[i0], 1);
            s_ebuf[i0][p0] = (tok << 1);
            s_wbuf[i0][p0] = w0;
            int p1 = atomicAdd(&s_cnt[i1], 1);
            s_ebuf[i1][p1] = (tok << 1) | 1;
            s_wbuf[i1][p1] = w1;

#pragma unroll
            for (int e = 0; e < NE; e++) atomicAdd(&s_sumP[e], p[e] * inv);
            float lse = m + logf(se);
            atomicAdd(&s_zsum, lse * lse);
        }
        __syncthreads();

        if (tid < NE) {
            s_base[tid] = atomicAdd(&g_cnt[tid], s_cnt[tid]);
            atomicAdd(&g_sumP[tid], s_sumP[tid]);
        }
        if (tid == NE) atomicAdd(&g_zsum, s_zsum);
        __syncthreads();

        {
            int e = wrp;
            int c = s_cnt[e], b = s_base[e];
            if (lane < c) {
                g_list[e * T_TOK + b + lane] = s_ebuf[e][lane];
                g_wgt [e * T_TOK + b + lane] = s_wbuf[e][lane];
            }
        }
        return;
    }

    if (blockIdx.x < RT_BLKS + ZERO_BLKS) {
        int i = (blockIdx.x - RT_BLKS) * 256 + threadIdx.x;
        ((float4*)out)[i] = make_float4(0.f, 0.f, 0.f, 0.f);
        return;
    }

    // convert x / gate / up to single fp16
    int i = (blockIdx.x - RT_BLKS - ZERO_BLKS) * 256 + threadIdx.x;
    if (i >= SPL_TOT) return;

    if (i < XN4) {
        cvt4_store(((const float4*)x)[i], g_x, (size_t)i);
    } else if (i < XN4 + WPER) {
        size_t j = i - XN4;
        cvt4_store(((const float4*)gw)[j], g_g, j);
    } else {
        size_t j = i - XN4 - WPER;
        cvt4_store(((const float4*)uw)[j], g_u, j);
    }
}

// ================= Phase A: gate/up fp16 single warp-MMA GEMM + down convert slice =================
// Block tile M=64 x N=64, K chunks of 64 (8 chunks), 2-stage pipeline, 3 blocks/SM.
// Stage: A 9216, Bg 9216, Bu 9216. Stage = 27648.
#define GU_STG  27648
#define GU_SMEM (1024 + 2*GU_STG)
#define GU_GX   16
#define GU_GY   64
#define DSPL_THREADS (GU_GX * GU_GY * 256)   // 262144

__global__ void __launch_bounds__(256, 3) gateup_mma_kernel(const float* __restrict__ dw) {
    // z == NE slice: convert down weights to single fp16
    if (blockIdx.z == NE) {
        int idx = (blockIdx.y * GU_GX + blockIdx.x) * 256 + threadIdx.x;
        for (int j = idx; j < WPER; j += DSPL_THREADS)
            cvt4_store(((const float4*)dw)[j], g_d, (size_t)j);
        return;
    }

    extern __shared__ char smem[];
    uint32_t sb = smem_u32(smem);
    int e = blockIdx.z;
    int cnt = g_cnt[e];
    int row0 = blockIdx.y * 64;
    if (row0 >= cnt) return;
    int col0 = blockIdx.x * 64;
    int tid = threadIdx.x, wid = tid >> 5, lid = tid & 31;
    int wm = wid >> 2, wn = wid & 3;
    int g = lid >> 2, t2 = (lid & 3) * 2;
    int* sTok = (int*)smem;

    for (int i = tid; i < 64; i += 256) {
        int r = row0 + i;
        sTok[i] = (r < cnt) ? g_list[e * T_TOK + r] : -1;
    }
    __syncthreads();

    const __half* bg = g_g + (size_t)e * DIM * FDIM;
    const __half* bu = g_u + (size_t)e * DIM * FDIM;

    float accg[2][2][4] = {}, accu[2][2][4] = {};

    auto stage = [&](int chunk) {
        int kt = chunk * 64;
        uint32_t bb = sb + 1024 + (uint32_t)(chunk & 1) * GU_STG;
        // A gathered: 512 cp16
#pragma unroll
        for (int it = 0; it < 2; it++) {
            int t = tid + it * 256;
            int row = t >> 3, seg = t & 7;
            int entry = sTok[row];
            uint32_t bytes = (entry >= 0) ? 16u : 0u;
            const __half* src = g_x
                + (size_t)((entry >= 0) ? (entry >> 1) : 0) * DIM + kt + seg * 8;
            cp16(bb + row * 144 + seg * 16, src, bytes);
        }
        // B gate + up: 1024 cp16
#pragma unroll
        for (int it = 0; it < 4; it++) {
            int t = tid + it * 256;
            int arr = t >> 9, u = t & 511, row = u >> 3, seg = u & 7;
            const __half* src = (arr ? bu : bg) + (size_t)(kt + row) * FDIM + col0 + seg * 8;
            cp16(bb + 9216 + arr * 9216 + row * 144 + seg * 16, src, 16u);
        }
    };

    uint32_t laneO = (uint32_t)(((lid & 7) + ((lid >> 3) & 1) * 8) * 144 + ((lid >> 4) & 1) * 16);

    stage(0); CP_COMMIT();
    for (int c = 0; c < 8; c++) {
        if (c + 1 < 8) { stage(c + 1); CP_COMMIT(); CP_WAITG(1); }
        else           { CP_WAITG(0); }
        __syncthreads();
        uint32_t bb = sb + 1024 + (uint32_t)(c & 1) * GU_STG;
        uint32_t aBase = bb + (uint32_t)(wm * 32) * 144 + laneO;
        uint32_t bBase = bb + 9216 + laneO + (uint32_t)(wn * 16) * 2;
#pragma unroll
        for (int kk = 0; kk < 4; kk++) {
            uint32_t ah[2][4];
#pragma unroll
            for (int mt = 0; mt < 2; mt++)
                ldsm_x4(ah[mt], aBase + mt * (16 * 144) + kk * 32);
            uint32_t ba = bBase + kk * (16 * 144);
            uint32_t bgr[4], bur[4];
            ldsm_x4_t(bgr, ba);
            ldsm_x4_t(bur, ba + 9216);
#pragma unroll
            for (int h = 0; h < 2; h++) {
#pragma unroll
                for (int mt = 0; mt < 2; mt++) {
                    mma_f16(accg[mt][h], ah[mt], bgr + h * 2);
                    mma_f16(accu[mt][h], ah[mt], bur + h * 2);
                }
            }
        }
        __syncthreads();
    }

    // epilogue: h = silu(gate)*up, single fp16
#pragma unroll
    for (int mt = 0; mt < 2; mt++) {
        int r0 = wm * 32 + mt * 16 + g;
        int e0 = sTok[r0], e1 = sTok[r0 + 8];
#pragma unroll
        for (int h = 0; h < 2; h++) {
            int colg = col0 + wn * 16 + h * 8 + t2;
            const float* dg = accg[mt][h];
            const float* du = accu[mt][h];
            if (e0 >= 0) {
                float h0 = du[0] * (dg[0] / (1.f + expf(-dg[0])));
                float h1 = du[1] * (dg[1] / (1.f + expf(-dg[1])));
                *(__half2*)(g_h + (size_t)e0 * FDIM + colg) = __floats2half2_rn(h0, h1);
            }
            if (e1 >= 0) {
                float h0 = du[2] * (dg[2] / (1.f + expf(-dg[2])));
                float h1 = du[3] * (dg[3] / (1.f + expf(-dg[3])));
                *(__half2*)(g_h + (size_t)e1 * FDIM + colg) = __floats2half2_rn(h0, h1);
            }
        }
    }
}

// ================= Phase B: down fp16 single warp-MMA GEMM — atomic epilogue =================
// Block tile M=64 x N=64, K=1024 in 16 chunks, 2-stage pipeline, 3 blocks/SM.
// Stage: A 9216, B 9216. Stage = 18432.
#define DN_STG  18432
#define DN_SMEM (1024 + 2*DN_STG)

__global__ void __launch_bounds__(256, 3) down_mma_kernel(float* __restrict__ out, int out_size) {
    if (blockIdx.x == 0 && blockIdx.y == 0 && blockIdx.z == 0 && threadIdx.x == 0) {
        float lb = 0.f;
#pragma unroll
        for (int e = 0; e < NE; e++)
            lb += ((float)g_cnt[e] / (float)NPAIR) * (g_sumP[e] / (float)T_TOK);
        out[out_size - 1] = 0.01f * (float)NE * lb + 0.001f * (g_zsum / (float)T_TOK);
    }

    extern __shared__ char smem[];
    uint32_t sb = smem_u32(smem);
    int e = blockIdx.z;
    int cnt = g_cnt[e];
    int row0 = blockIdx.y * 64;
    if (row0 >= cnt) return;
    int col0 = blockIdx.x * 64;
    int tid = threadIdx.x, wid = tid >> 5, lid = tid & 31;
    int wm = wid >> 2, wn = wid & 3;
    int g = lid >> 2, t2 = (lid & 3) * 2;
    int*   sTok = (int*)smem;
    float* sW   = (float*)(smem + 256);

    for (int i = tid; i < 64; i += 256) {
        int r = row0 + i;
        sTok[i] = (r < cnt) ? g_list[e * T_TOK + r] : -1;
        sW[i]   = (r < cnt) ? g_wgt [e * T_TOK + r] : 0.f;
    }
    __syncthreads();

    const __half* dwp = g_d + (size_t)e * FDIM * DIM;

    float acc[2][2][4] = {};

    auto stage = [&](int chunk) {
        int kt = chunk * 64;
        uint32_t bb = sb + 1024 + (uint32_t)(chunk & 1) * DN_STG;
        // A hidden gathered: 512 cp16
#pragma unroll
        for (int it = 0; it < 2; it++) {
            int t = tid + it * 256;
            int row = t >> 3, seg = t & 7;
            int entry = sTok[row];
            uint32_t bytes = (entry >= 0) ? 16u : 0u;
            const __half* src = g_h
                + (size_t)((entry >= 0) ? entry : 0) * FDIM + kt + seg * 8;
            cp16(bb + row * 144 + seg * 16, src, bytes);
        }
        // B: 512 cp16
#pragma unroll
        for (int it = 0; it < 2; it++) {
            int t = tid + it * 256;
            int row = t >> 3, seg = t & 7;
            const __half* src = dwp + (size_t)(kt + row) * DIM + col0 + seg * 8;
            cp16(bb + 9216 + row * 144 + seg * 16, src, 16u);
        }
    };

    uint32_t laneO = (uint32_t)(((lid & 7) + ((lid >> 3) & 1) * 8) * 144 + ((lid >> 4) & 1) * 16);

    stage(0); CP_COMMIT();
    for (int c = 0; c < 16; c++) {
        if (c + 1 < 16) { stage(c + 1); CP_COMMIT(); CP_WAITG(1); }
        else            { CP_WAITG(0); }
        __syncthreads();
        uint32_t bb = sb + 1024 + (uint32_t)(c & 1) * DN_STG;
        uint32_t aBase = bb + (uint32_t)(wm * 32) * 144 + laneO;
        uint32_t bBase = bb + 9216 + laneO + (uint32_t)(wn * 16) * 2;
#pragma unroll
        for (int kk = 0; kk < 4; kk++) {
            uint32_t ah[2][4];
#pragma unroll
            for (int mt = 0; mt < 2; mt++)
                ldsm_x4(ah[mt], aBase + mt * (16 * 144) + kk * 32);
            uint32_t bh[4];
            ldsm_x4_t(bh, bBase + kk * (16 * 144));
#pragma unroll
            for (int h = 0; h < 2; h++) {
#pragma unroll
                for (int mt = 0; mt < 2; mt++)
                    mma_f16(acc[mt][h], ah[mt], bh + h * 2);
            }
        }
        __syncthreads();
    }

    // epilogue: scale by combine weight, atomicAdd into out (exactly 2 adds per element)
#pragma unroll
    for (int mt = 0; mt < 2; mt++) {
        int r0 = wm * 32 + mt * 16 + g;
        int e0 = sTok[r0], e1 = sTok[r0 + 8];
        float w0 = sW[r0], w1 = sW[r0 + 8];
#pragma unroll
        for (int h = 0; h < 2; h++) {
            int cg = col0 + wn * 16 + h * 8 + t2;
            const float* d = acc[mt][h];
            if (e0 >= 0) {
                float* op = out + (size_t)(e0 >> 1) * DIM + cg;
                atomicAdd(op,     w0 * d[0]);
                atomicAdd(op + 1, w0 * d[1]);
            }
            if (e1 >= 0) {
                float* op = out + (size_t)(e1 >> 1) * DIM + cg;
                atomicAdd(op,     w1 * d[2]);
                atomicAdd(op + 1, w1 * d[3]);
            }
        }
    }
}

// ---------------- reset accumulators for the next launch (graph replay) ----------------
__global__ void reset_kernel() {
    int i = threadIdx.x;
    if (i < NE) { g_cnt[i] = 0; g_sumP[i] = 0.f; }
    if (i == 0) g_zsum = 0.f;
}

// ---------------- launch ----------------
extern "C" void kernel_launch(void* const* d_in, const int* in_sizes, int n_in,
                              void* d_out, int out_size) {
    const float* x  = (const float*)d_in[0];
    const float* rw = (const float*)d_in[1];
    const float* gw = (const float*)d_in[2];
    const float* uw = (const float*)d_in[3];
    const float* dw = (const float*)d_in[4];
    float* out = (float*)d_out;

    cudaFuncSetAttribute(gateup_mma_kernel, cudaFuncAttributeMaxDynamicSharedMemorySize, GU_SMEM);
    cudaFuncSetAttribute(down_mma_kernel,   cudaFuncAttributeMaxDynamicSharedMemorySize, DN_SMEM);

    prep_router_kernel<<<RT_BLKS + ZERO_BLKS + SPL_BLKS, 256>>>(x, rw, gw, uw, out);
    gateup_mma_kernel<<<dim3(GU_GX, GU_GY, NE + 1), 256, GU_SMEM>>>(dw);
    down_mma_kernel<<<dim3(DIM / 64, T_TOK / 64, NE), 256, DN_SMEM>>>(out, out_size);
    reset_kernel<<<1, 32>>>();
}